// round 3
// baseline (speedup 1.0000x reference)
#include <cuda_runtime.h>

#define BATCH  8
#define SEQ    1024
#define DMODEL 256
#define NHD    8
#define DKH    32

// ---------------- scratch (device globals; no allocations) ----------------
__device__ float g_q[(size_t)BATCH * SEQ * DMODEL];
__device__ float g_k[(size_t)BATCH * SEQ * DMODEL];
__device__ float g_v[(size_t)BATCH * SEQ * DMODEL];
__device__ float g_scores[(size_t)BATCH * NHD * SEQ * SEQ];  // 268 MB
__device__ float g_ctx[(size_t)BATCH * SEQ * DMODEL];
__device__ float g_tmp[(size_t)BATCH * SEQ * DMODEL];
__device__ unsigned short g_idx[SEQ * SEQ];
__device__ float g_cexp[NHD * 960];                          // exp(dist_bias+dir_bias)
__device__ float g_part[(size_t)64 * SEQ * 16 * 4];          // per (bh,row,chunk): m,zp,zb
__device__ float4 g_stats[(size_t)64 * SEQ];                 // per (bh,row): M, 1/Zp, 1/Zb

// ---------------- tf32 mma helpers ----------------
__device__ __forceinline__ unsigned f2tf(float f) {
    unsigned u;
    asm("cvt.rna.tf32.f32 %0, %1;" : "=r"(u) : "f"(f));
    return u;
}
__device__ __forceinline__ void mma_tf32(float* d, const unsigned* a, const unsigned* b) {
    asm volatile(
        "mma.sync.aligned.m16n8k8.row.col.f32.tf32.tf32.f32 "
        "{%0,%1,%2,%3}, {%4,%5,%6,%7}, {%8,%9}, {%0,%1,%2,%3};"
        : "+f"(d[0]), "+f"(d[1]), "+f"(d[2]), "+f"(d[3])
        : "r"(a[0]), "r"(a[1]), "r"(a[2]), "r"(a[3]), "r"(b[0]), "r"(b[1]));
}

// ---------------- bias-exp table + spatial index precompute ----------------
__global__ void comb_kernel(const float* __restrict__ dist_bias,
                            const float* __restrict__ dir_bias) {
    int t = blockIdx.x * 256 + threadIdx.x;
    if (t < NHD * 960) {
        int h = t / 960, r = t % 960;
        int di = r >> 4, dr = r & 15;
        g_cexp[t] = __expf(dist_bias[di * NHD + h] + dir_bias[dr * NHD + h]);
    }
}

__global__ void idx_kernel() {
    int e = blockIdx.x * 256 + threadIdx.x;
    int i = e >> 10, j = e & 1023;
    int h1 = i >> 5, w1 = i & 31, h2 = j >> 5, w2 = j & 31;
    int dh = h2 - h1, dw = w2 - w1;
    int n = dh * dh + dw * dw;
    int di = (int)sqrtf((float)n);
    if (di > 59) di = 59;
    int ex = -dw, ey = -dh, dir;
    if (ey == 0)            dir = (ex >= 0) ? 0 : 8;
    else if (ex == 0)       dir = (ey > 0) ? 4 : 12;
    else if (ex == ey)      dir = (ex > 0) ? 2 : 10;
    else if (ex == -ey)     dir = (ex > 0) ? 14 : 6;
    else {
        float a = atan2f((float)ey, (float)ex);
        if (a < 0.0f) a += 6.28318530717958647692f;
        dir = (int)(a * 2.54647908947032537164f);
        if (dir > 15) dir = 15;
    }
    g_idx[e] = (unsigned short)(di * 16 + dir);
}

// ---------------- smem tile loader: 128 rows x 32 cols, k-major [k][m] ----------------
__device__ __forceinline__ void load_tile(const float* __restrict__ g, int ld,
                                          int r0, int kt, float (*S)[132]) {
    int lr = threadIdx.x >> 3, lc = (threadIdx.x & 7) * 4;
#pragma unroll
    for (int rr = 0; rr < 4; rr++) {
        int row = lr + rr * 32;
        float4 v = *(const float4*)(g + (size_t)(r0 + row) * ld + kt + lc);
        S[lc + 0][row] = v.x; S[lc + 1][row] = v.y;
        S[lc + 2][row] = v.z; S[lc + 3][row] = v.w;
    }
}

// ---------------- tf32 GEMM core: 128x128 tile, C = A(MxK) @ B(NxK)^T ----------------
__device__ __forceinline__ void gemm_core_tf32(
    const float* __restrict__ gA, const float* __restrict__ gB,
    int lda, int ldb, int m0, int n0, int K,
    float (&acc)[2][8][4], float (*As)[132], float (*Bs)[132])
{
    const int lane = threadIdx.x & 31, wid = threadIdx.x >> 5;
    const int wm = (wid & 3) * 32, wn = (wid >> 2) * 64;
    const int qr = lane >> 2, qc = lane & 3;

    for (int kt = 0; kt < K; kt += 32) {
        load_tile(gA, lda, m0, kt, As);
        load_tile(gB, ldb, n0, kt, Bs);
        __syncthreads();
#pragma unroll
        for (int kb = 0; kb < 32; kb += 8) {
            unsigned afr[2][4], bfr[8][2];
#pragma unroll
            for (int mi = 0; mi < 2; mi++) {
                int r = wm + mi * 16 + qr;
                afr[mi][0] = f2tf(As[kb + qc][r]);
                afr[mi][1] = f2tf(As[kb + qc][r + 8]);
                afr[mi][2] = f2tf(As[kb + 4 + qc][r]);
                afr[mi][3] = f2tf(As[kb + 4 + qc][r + 8]);
            }
#pragma unroll
            for (int ni = 0; ni < 8; ni++) {
                int nn = wn + ni * 8 + qr;
                bfr[ni][0] = f2tf(Bs[kb + qc][nn]);
                bfr[ni][1] = f2tf(Bs[kb + 4 + qc][nn]);
            }
#pragma unroll
            for (int mi = 0; mi < 2; mi++)
#pragma unroll
                for (int ni = 0; ni < 8; ni++)
                    mma_tf32(acc[mi][ni], afr[mi], bfr[ni]);
        }
        __syncthreads();
    }
}

// ---------------- QKV projection ----------------
__global__ __launch_bounds__(256) void proj_kernel(
    const float* __restrict__ x,
    const float* __restrict__ w0, const float* __restrict__ w1, const float* __restrict__ w2,
    const float* __restrict__ b0, const float* __restrict__ b1, const float* __restrict__ b2)
{
    __shared__ __align__(16) float As[32][132];
    __shared__ __align__(16) float Bs[32][132];
    int z = blockIdx.z;
    const float* W  = (z == 0) ? w0 : ((z == 1) ? w1 : w2);
    const float* bi = (z == 0) ? b0 : ((z == 1) ? b1 : b2);
    float* out      = (z == 0) ? g_q : ((z == 1) ? g_k : g_v);

    int m0 = blockIdx.y * 128, n0 = blockIdx.x * 128;
    float acc[2][8][4] = {};
    gemm_core_tf32(x, W, DMODEL, DMODEL, m0, n0, DMODEL, acc, As, Bs);

    const int lane = threadIdx.x & 31, wid = threadIdx.x >> 5;
    const int wm = (wid & 3) * 32, wn = (wid >> 2) * 64;
#pragma unroll
    for (int mi = 0; mi < 2; mi++)
#pragma unroll
        for (int ni = 0; ni < 8; ni++) {
            int row = m0 + wm + mi * 16 + (lane >> 2);
            int col = n0 + wn + ni * 8 + (lane & 3) * 2;
            float2 bv = *(const float2*)(bi + col);
            float2 o0 = {acc[mi][ni][0] + bv.x, acc[mi][ni][1] + bv.y};
            float2 o1 = {acc[mi][ni][2] + bv.x, acc[mi][ni][3] + bv.y};
            *(float2*)(out + (size_t)row * DMODEL + col)       = o0;
            *(float2*)(out + (size_t)(row + 8) * DMODEL + col) = o1;
        }
}

// ---------------- qk: scores + per-chunk softmax partials (plain & biased) ----------------
__global__ __launch_bounds__(256) void qk_kernel() {
    __shared__ __align__(16) float As[32][132];
    __shared__ __align__(16) float Bs[32][132];
    __shared__ float cexp_s[960];
    int bh = blockIdx.z;
    int b = bh >> 3, h = bh & 7;
    const float* A = g_q + (size_t)b * SEQ * DMODEL + h * DKH;
    const float* B = g_k + (size_t)b * SEQ * DMODEL + h * DKH;
    float* C = g_scores + (size_t)bh * SEQ * SEQ;

    for (int t = threadIdx.x; t < 960; t += 256) cexp_s[t] = g_cexp[h * 960 + t];

    int m0 = blockIdx.y * 128, n0 = blockIdx.x * 128;
    float acc[2][8][4] = {};
    gemm_core_tf32(A, B, DMODEL, DMODEL, m0, n0, DKH, acc, As, Bs);

    const float scale = 0.17677669529663688f;
    const int lane = threadIdx.x & 31, wid = threadIdx.x >> 5;
    const int wm = (wid & 3) * 32, wn = (wid >> 2) * 64;
    const int qr = lane >> 2, qc = lane & 3;

#pragma unroll
    for (int mi = 0; mi < 2; mi++)
#pragma unroll
        for (int ni = 0; ni < 8; ni++)
#pragma unroll
            for (int k = 0; k < 4; k++) acc[mi][ni][k] *= scale;

    // write scores
#pragma unroll
    for (int mi = 0; mi < 2; mi++)
#pragma unroll
        for (int ni = 0; ni < 8; ni++) {
            int row = m0 + wm + mi * 16 + qr;
            int col = n0 + wn + ni * 8 + qc * 2;
            float2 o0 = {acc[mi][ni][0], acc[mi][ni][1]};
            float2 o1 = {acc[mi][ni][2], acc[mi][ni][3]};
            *(float2*)(C + (size_t)row * SEQ + col)       = o0;
            *(float2*)(C + (size_t)(row + 8) * SEQ + col) = o1;
        }

    // per-64-col softmax partials: m, sum(exp(s-m)), sum(exp(s-m)*cexp[idx])
    int chunk = (n0 + wn) >> 6;
#pragma unroll
    for (int mi = 0; mi < 2; mi++)
#pragma unroll
        for (int half = 0; half < 2; half++) {
            int row = m0 + wm + mi * 16 + qr + half * 8;
            float m = -1e30f;
#pragma unroll
            for (int ni = 0; ni < 8; ni++)
                m = fmaxf(m, fmaxf(acc[mi][ni][half * 2], acc[mi][ni][half * 2 + 1]));
            m = fmaxf(m, __shfl_xor_sync(0xffffffffu, m, 1));
            m = fmaxf(m, __shfl_xor_sync(0xffffffffu, m, 2));
            const unsigned short* ip = g_idx + (size_t)row * SEQ + n0 + wn + qc * 2;
            float zp = 0.f, zb = 0.f;
#pragma unroll
            for (int ni = 0; ni < 8; ni++) {
                float E0 = __expf(acc[mi][ni][half * 2]     - m);
                float E1 = __expf(acc[mi][ni][half * 2 + 1] - m);
                zp += E0 + E1;
                zb += E0 * cexp_s[ip[ni * 8]] + E1 * cexp_s[ip[ni * 8 + 1]];
            }
            zp += __shfl_xor_sync(0xffffffffu, zp, 1);
            zp += __shfl_xor_sync(0xffffffffu, zp, 2);
            zb += __shfl_xor_sync(0xffffffffu, zb, 1);
            zb += __shfl_xor_sync(0xffffffffu, zb, 2);
            if (qc == 0) {
                size_t o = (((size_t)bh * SEQ + row) * 16 + chunk) * 4;
                g_part[o] = m; g_part[o + 1] = zp; g_part[o + 2] = zb;
            }
        }
}

// ---------------- merge 16 chunk-partials per row ----------------
__global__ __launch_bounds__(256) void combine_kernel() {
    int row = blockIdx.x * 256 + threadIdx.x;    // 0..65535 = bh*1024+i
    const float4* p = (const float4*)(g_part + (size_t)row * 64);
    float4 c[16];
#pragma unroll
    for (int t = 0; t < 16; t++) c[t] = p[t];
    float M = c[0].x;
#pragma unroll
    for (int t = 1; t < 16; t++) M = fmaxf(M, c[t].x);
    float zp = 0.f, zb = 0.f;
#pragma unroll
    for (int t = 0; t < 16; t++) {
        float w = __expf(c[t].x - M);
        zp += c[t].y * w;
        zb += c[t].z * w;
    }
    g_stats[row] = make_float4(M, 1.0f / zp, 1.0f / zb, 0.f);
}

// ---------------- fused: probs (biased) @ V -> ctx, plain probs -> attn_w ----------------
__global__ __launch_bounds__(128, 4) void attn_kernel(float* __restrict__ attn_w) {
    __shared__ __align__(16) float Ps2[16][132];   // probs, row-major [m][k], tf32 bits
    __shared__ __align__(16) float Vs[128][40];    // V tile [k][n], tf32 bits
    __shared__ float4 stats_s[8][16];
    __shared__ float buf[16][33];

    int b = blockIdx.y;
    int i0 = blockIdx.x * 16;
    int t = threadIdx.x, lane = t & 31, w = t >> 5;
    int qr = lane >> 2, qc = lane & 3;
    int wn = (w & 1) * 16, wk = (w >> 1) * 64;

    { int h = t >> 4, r = t & 15;
      stats_s[h][r] = g_stats[(size_t)(b * 8 + h) * SEQ + i0 + r]; }
    __syncthreads();

    float acc[8][2][4];
#pragma unroll
    for (int h = 0; h < 8; h++)
#pragma unroll
        for (int ni = 0; ni < 2; ni++)
#pragma unroll
            for (int k = 0; k < 4; k++) acc[h][ni][k] = 0.f;

    const int c = t;   // column owner 0..127

    for (int jt = 0; jt < 8; jt++) {
        int j0 = jt * 128;
        unsigned short idxl[16];
#pragma unroll
        for (int rr = 0; rr < 16; rr++)
            idxl[rr] = g_idx[(size_t)(i0 + rr) * SEQ + j0 + c];
        float aw[16];
#pragma unroll
        for (int rr = 0; rr < 16; rr++) aw[rr] = 0.f;

        for (int h = 0; h < 8; h++) {
            int bh = b * 8 + h;
            // V tile: one row per thread, convert to tf32
            {
                const float* vp = g_v + ((size_t)b * SEQ + j0 + t) * DMODEL + h * DKH;
#pragma unroll
                for (int dv = 0; dv < 32; dv += 4) {
                    float4 v = *(const float4*)(vp + dv);
                    float4 cv;
                    cv.x = __uint_as_float(f2tf(v.x));
                    cv.y = __uint_as_float(f2tf(v.y));
                    cv.z = __uint_as_float(f2tf(v.z));
                    cv.w = __uint_as_float(f2tf(v.w));
                    *(float4*)&Vs[t][dv] = cv;
                }
            }
            const float* cx = g_cexp + h * 960;
#pragma unroll
            for (int rr = 0; rr < 16; rr++) {
                float s = g_scores[((size_t)bh * SEQ + i0 + rr) * SEQ + j0 + c];
                float4 st = stats_s[h][rr];
                float E = __expf(s - st.x);
                aw[rr] += E * st.y;
                float pb = E * __ldg(cx + idxl[rr]) * st.z;
                Ps2[rr][c] = __uint_as_float(f2tf(pb));
            }
            __syncthreads();
            // PV mma: warp (wn,wk) computes 16x16 over its 64-wide k slice
#pragma unroll
            for (int kb = 0; kb < 64; kb += 8) {
                int k0 = wk + kb;
                unsigned afr[4];
                afr[0] = __float_as_uint(Ps2[qr][k0 + qc]);
                afr[1] = __float_as_uint(Ps2[qr + 8][k0 + qc]);
                afr[2] = __float_as_uint(Ps2[qr][k0 + 4 + qc]);
                afr[3] = __float_as_uint(Ps2[qr + 8][k0 + 4 + qc]);
#pragma unroll
                for (int ni = 0; ni < 2; ni++) {
                    unsigned bfr[2];
                    bfr[0] = __float_as_uint(Vs[k0 + qc][wn + ni * 8 + qr]);
                    bfr[1] = __float_as_uint(Vs[k0 + 4 + qc][wn + ni * 8 + qr]);
                    mma_tf32(acc[h][ni], afr, bfr);
                }
            }
            __syncthreads();
        }
#pragma unroll
        for (int rr = 0; rr < 16; rr++)
            attn_w[((size_t)b * SEQ + i0 + rr) * SEQ + j0 + c] = aw[rr] * 0.125f;
    }

    // combine k-halves and write ctx
    for (int h = 0; h < 8; h++) {
        if (w < 2) {
#pragma unroll
            for (int ni = 0; ni < 2; ni++) {
                buf[qr][wn + ni * 8 + qc * 2]     = acc[h][ni][0];
                buf[qr][wn + ni * 8 + qc * 2 + 1] = acc[h][ni][1];
                buf[qr + 8][wn + ni * 8 + qc * 2]     = acc[h][ni][2];
                buf[qr + 8][wn + ni * 8 + qc * 2 + 1] = acc[h][ni][3];
            }
        }
        __syncthreads();
        if (w >= 2) {
#pragma unroll
            for (int ni = 0; ni < 2; ni++) {
                buf[qr][wn + ni * 8 + qc * 2]     += acc[h][ni][0];
                buf[qr][wn + ni * 8 + qc * 2 + 1] += acc[h][ni][1];
                buf[qr + 8][wn + ni * 8 + qc * 2]     += acc[h][ni][2];
                buf[qr + 8][wn + ni * 8 + qc * 2 + 1] += acc[h][ni][3];
            }
        }
        __syncthreads();
        {
            int r = t >> 3, d = (t & 7) * 4;
            float4 o = {buf[r][d], buf[r][d + 1], buf[r][d + 2], buf[r][d + 3]};
            *(float4*)(g_ctx + ((size_t)b * SEQ + i0 + r) * DMODEL + h * DKH + d) = o;
        }
        __syncthreads();
    }
}

// ---------------- out-proj + residual ----------------
__global__ __launch_bounds__(256) void outproj_kernel(
    const float* __restrict__ x, const float* __restrict__ wo, const float* __restrict__ bo)
{
    __shared__ __align__(16) float As[32][132];
    __shared__ __align__(16) float Bs[32][132];
    int m0 = blockIdx.y * 128, n0 = blockIdx.x * 128;
    float acc[2][8][4] = {};
    gemm_core_tf32(g_ctx, wo, DMODEL, DMODEL, m0, n0, DMODEL, acc, As, Bs);

    const int lane = threadIdx.x & 31, wid = threadIdx.x >> 5;
    const int wm = (wid & 3) * 32, wn = (wid >> 2) * 64;
#pragma unroll
    for (int mi = 0; mi < 2; mi++)
#pragma unroll
        for (int ni = 0; ni < 8; ni++) {
            int row = m0 + wm + mi * 16 + (lane >> 2);
            int col = n0 + wn + ni * 8 + (lane & 3) * 2;
            float2 bv = *(const float2*)(bo + col);
            float2 x0 = *(const float2*)(x + (size_t)row * DMODEL + col);
            float2 x1 = *(const float2*)(x + (size_t)(row + 8) * DMODEL + col);
            float2 o0 = {acc[mi][ni][0] + bv.x + x0.x, acc[mi][ni][1] + bv.y + x0.y};
            float2 o1 = {acc[mi][ni][2] + bv.x + x1.x, acc[mi][ni][3] + bv.y + x1.y};
            *(float2*)(g_tmp + (size_t)row * DMODEL + col)       = o0;
            *(float2*)(g_tmp + (size_t)(row + 8) * DMODEL + col) = o1;
        }
}

// ---------------- LayerNorm ----------------
__device__ __forceinline__ float warp_red_sum(float v) {
#pragma unroll
    for (int o = 16; o; o >>= 1) v += __shfl_xor_sync(0xffffffffu, v, o);
    return v;
}
__global__ __launch_bounds__(256) void ln_kernel(
    const float* __restrict__ lng, const float* __restrict__ lnb, float* __restrict__ y)
{
    __shared__ float red[8];
    size_t m = blockIdx.x;
    int tid = threadIdx.x, wd = tid >> 5, l = tid & 31;
    float v = g_tmp[m * DMODEL + tid];
    float s = warp_red_sum(v);
    if (l == 0) red[wd] = s;
    __syncthreads();
    float mu = 0.f;
#pragma unroll
    for (int k = 0; k < 8; k++) mu += red[k];
    mu *= (1.0f / DMODEL);
    __syncthreads();
    float d = v - mu;
    float sq = warp_red_sum(d * d);
    if (l == 0) red[wd] = sq;
    __syncthreads();
    float var = 0.f;
#pragma unroll
    for (int k = 0; k < 8; k++) var += red[k];
    var *= (1.0f / DMODEL);
    y[m * DMODEL + tid] = d * rsqrtf(var + 1e-5f) * lng[tid] + lnb[tid];
}

// ---------------- launch ----------------
extern "C" void kernel_launch(void* const* d_in, const int* in_sizes, int n_in,
                              void* d_out, int out_size) {
    const float* x    = (const float*)d_in[0];
    const float* wq   = (const float*)d_in[1];
    const float* bq   = (const float*)d_in[2];
    const float* wk   = (const float*)d_in[3];
    const float* bk   = (const float*)d_in[4];
    const float* wv   = (const float*)d_in[5];
    const float* bv   = (const float*)d_in[6];
    const float* wo   = (const float*)d_in[7];
    const float* bo   = (const float*)d_in[8];
    const float* lng  = (const float*)d_in[9];
    const float* lnb  = (const float*)d_in[10];
    const float* dist = (const float*)d_in[11];
    const float* dirb = (const float*)d_in[12];

    float* y_out  = (float*)d_out;
    float* aw_out = y_out + (size_t)BATCH * SEQ * DMODEL;

    comb_kernel<<<30, 256>>>(dist, dirb);
    idx_kernel<<<4096, 256>>>();
    proj_kernel<<<dim3(2, 64, 3), 256>>>(x, wq, wk, wv, bq, bk, bv);
    qk_kernel<<<dim3(8, 8, 64), 256>>>();
    combine_kernel<<<256, 256>>>();
    attn_kernel<<<dim3(64, 8), 128>>>(aw_out);
    outproj_kernel<<<dim3(2, 64, 1), 256>>>(x, wo, bo);
    ln_kernel<<<8192, 256>>>(lng, lnb, y_out);
}

// round 4
// speedup vs baseline: 1.5890x; 1.5890x over previous
#include <cuda_runtime.h>
#include <cuda_fp16.h>

#define BATCH  8
#define SEQ    1024
#define DMODEL 256
#define NHD    8
#define DKH    32

// ---------------- scratch (device globals; no allocations) ----------------
__device__ float g_q[(size_t)BATCH * SEQ * DMODEL];
__device__ float g_k[(size_t)BATCH * SEQ * DMODEL];
__device__ float g_v[(size_t)BATCH * SEQ * DMODEL];
__device__ __half g_sh[(size_t)BATCH * NHD * SEQ * SEQ];   // scores then probs, fp16 (134 MB)
__device__ float g_ctx[(size_t)BATCH * SEQ * DMODEL];
__device__ float g_tmp[(size_t)BATCH * SEQ * DMODEL];
__device__ unsigned short g_idx[SEQ * SEQ];
__device__ float g_cexp[NHD * 960];                        // exp(dist_bias + dir_bias)

// ---------------- tf32 mma helpers ----------------
__device__ __forceinline__ unsigned f2tf(float f) {
    unsigned u;
    asm("cvt.rna.tf32.f32 %0, %1;" : "=r"(u) : "f"(f));
    return u;
}
__device__ __forceinline__ void mma_tf32(float* d, const unsigned* a, const unsigned* b) {
    asm volatile(
        "mma.sync.aligned.m16n8k8.row.col.f32.tf32.tf32.f32 "
        "{%0,%1,%2,%3}, {%4,%5,%6,%7}, {%8,%9}, {%0,%1,%2,%3};"
        : "+f"(d[0]), "+f"(d[1]), "+f"(d[2]), "+f"(d[3])
        : "r"(a[0]), "r"(a[1]), "r"(a[2]), "r"(a[3]), "r"(b[0]), "r"(b[1]));
}

// ---------------- bias-exp table + spatial index precompute ----------------
__global__ void comb_kernel(const float* __restrict__ dist_bias,
                            const float* __restrict__ dir_bias) {
    int t = blockIdx.x * 256 + threadIdx.x;
    if (t < NHD * 960) {
        int h = t / 960, r = t % 960;
        int di = r >> 4, dr = r & 15;
        g_cexp[t] = __expf(dist_bias[di * NHD + h] + dir_bias[dr * NHD + h]);
    }
}

__global__ void idx_kernel() {
    int e = blockIdx.x * 256 + threadIdx.x;
    int i = e >> 10, j = e & 1023;
    int h1 = i >> 5, w1 = i & 31, h2 = j >> 5, w2 = j & 31;
    int dh = h2 - h1, dw = w2 - w1;
    int n = dh * dh + dw * dw;
    int di = (int)sqrtf((float)n);
    if (di > 59) di = 59;
    int ex = -dw, ey = -dh, dir;
    if (ey == 0)            dir = (ex >= 0) ? 0 : 8;
    else if (ex == 0)       dir = (ey > 0) ? 4 : 12;
    else if (ex == ey)      dir = (ex > 0) ? 2 : 10;
    else if (ex == -ey)     dir = (ex > 0) ? 14 : 6;
    else {
        float a = atan2f((float)ey, (float)ex);
        if (a < 0.0f) a += 6.28318530717958647692f;
        dir = (int)(a * 2.54647908947032537164f);
        if (dir > 15) dir = 15;
    }
    g_idx[e] = (unsigned short)(di * 16 + dir);
}

// ---------------- smem tile loaders: 128 rows x 32 cols, k-major [k][m] ----------------
__device__ __forceinline__ void load_tile(const float* __restrict__ g, int ld,
                                          int r0, int kt, float (*S)[132]) {
    int lr = threadIdx.x >> 3, lc = (threadIdx.x & 7) * 4;
#pragma unroll
    for (int rr = 0; rr < 4; rr++) {
        int row = lr + rr * 32;
        float4 v = *(const float4*)(g + (size_t)(r0 + row) * ld + kt + lc);
        S[lc + 0][row] = v.x; S[lc + 1][row] = v.y;
        S[lc + 2][row] = v.z; S[lc + 3][row] = v.w;
    }
}

__device__ __forceinline__ void load_tile_h(const __half* __restrict__ g, int ld,
                                            int r0, int kt, float (*S)[132]) {
    int lr = threadIdx.x >> 3, lc = (threadIdx.x & 7) * 4;
#pragma unroll
    for (int rr = 0; rr < 4; rr++) {
        int row = lr + rr * 32;
        const __half2* p = (const __half2*)(g + (size_t)(r0 + row) * ld + kt + lc);
        float2 f01 = __half22float2(p[0]);
        float2 f23 = __half22float2(p[1]);
        S[lc + 0][row] = f01.x; S[lc + 1][row] = f01.y;
        S[lc + 2][row] = f23.x; S[lc + 3][row] = f23.y;
    }
}

// ---------------- tf32 GEMM core: 128x128 tile, C = A(MxK) @ B(NxK)^T ----------------
__device__ __forceinline__ void gemm_core_tf32(
    const float* __restrict__ gA, const float* __restrict__ gB,
    int lda, int ldb, int m0, int n0, int K,
    float (&acc)[2][8][4], float (*As)[132], float (*Bs)[132])
{
    const int lane = threadIdx.x & 31, wid = threadIdx.x >> 5;
    const int wm = (wid & 3) * 32, wn = (wid >> 2) * 64;
    const int qr = lane >> 2, qc = lane & 3;

    for (int kt = 0; kt < K; kt += 32) {
        load_tile(gA, lda, m0, kt, As);
        load_tile(gB, ldb, n0, kt, Bs);
        __syncthreads();
#pragma unroll
        for (int kb = 0; kb < 32; kb += 8) {
            unsigned afr[2][4], bfr[8][2];
#pragma unroll
            for (int mi = 0; mi < 2; mi++) {
                int r = wm + mi * 16 + qr;
                afr[mi][0] = f2tf(As[kb + qc][r]);
                afr[mi][1] = f2tf(As[kb + qc][r + 8]);
                afr[mi][2] = f2tf(As[kb + 4 + qc][r]);
                afr[mi][3] = f2tf(As[kb + 4 + qc][r + 8]);
            }
#pragma unroll
            for (int ni = 0; ni < 8; ni++) {
                int nn = wn + ni * 8 + qr;
                bfr[ni][0] = f2tf(Bs[kb + qc][nn]);
                bfr[ni][1] = f2tf(Bs[kb + 4 + qc][nn]);
            }
#pragma unroll
            for (int mi = 0; mi < 2; mi++)
#pragma unroll
                for (int ni = 0; ni < 8; ni++)
                    mma_tf32(acc[mi][ni], afr[mi], bfr[ni]);
        }
        __syncthreads();
    }
}

// ---------------- QKV projection ----------------
__global__ __launch_bounds__(256) void proj_kernel(
    const float* __restrict__ x,
    const float* __restrict__ w0, const float* __restrict__ w1, const float* __restrict__ w2,
    const float* __restrict__ b0, const float* __restrict__ b1, const float* __restrict__ b2)
{
    __shared__ __align__(16) float As[32][132];
    __shared__ __align__(16) float Bs[32][132];
    int z = blockIdx.z;
    const float* W  = (z == 0) ? w0 : ((z == 1) ? w1 : w2);
    const float* bi = (z == 0) ? b0 : ((z == 1) ? b1 : b2);
    float* out      = (z == 0) ? g_q : ((z == 1) ? g_k : g_v);

    int m0 = blockIdx.y * 128, n0 = blockIdx.x * 128;
    float acc[2][8][4] = {};
    gemm_core_tf32(x, W, DMODEL, DMODEL, m0, n0, DMODEL, acc, As, Bs);

    const int lane = threadIdx.x & 31, wid = threadIdx.x >> 5;
    const int wm = (wid & 3) * 32, wn = (wid >> 2) * 64;
#pragma unroll
    for (int mi = 0; mi < 2; mi++)
#pragma unroll
        for (int ni = 0; ni < 8; ni++) {
            int row = m0 + wm + mi * 16 + (lane >> 2);
            int col = n0 + wn + ni * 8 + (lane & 3) * 2;
            float2 bv = *(const float2*)(bi + col);
            float2 o0 = {acc[mi][ni][0] + bv.x, acc[mi][ni][1] + bv.y};
            float2 o1 = {acc[mi][ni][2] + bv.x, acc[mi][ni][3] + bv.y};
            *(float2*)(out + (size_t)row * DMODEL + col)       = o0;
            *(float2*)(out + (size_t)(row + 8) * DMODEL + col) = o1;
        }
}

// ---------------- scores = scale * q @ k^T, stored fp16 ----------------
__global__ __launch_bounds__(256) void qk_kernel() {
    __shared__ __align__(16) float As[32][132];
    __shared__ __align__(16) float Bs[32][132];
    int bh = blockIdx.z;
    int b = bh >> 3, h = bh & 7;
    const float* A = g_q + (size_t)b * SEQ * DMODEL + h * DKH;
    const float* B = g_k + (size_t)b * SEQ * DMODEL + h * DKH;
    __half* C = g_sh + (size_t)bh * SEQ * SEQ;

    int m0 = blockIdx.y * 128, n0 = blockIdx.x * 128;
    float acc[2][8][4] = {};
    gemm_core_tf32(A, B, DMODEL, DMODEL, m0, n0, DKH, acc, As, Bs);

    const float scale = 0.17677669529663688f;
    const int lane = threadIdx.x & 31, wid = threadIdx.x >> 5;
    const int wm = (wid & 3) * 32, wn = (wid >> 2) * 64;
#pragma unroll
    for (int mi = 0; mi < 2; mi++)
#pragma unroll
        for (int ni = 0; ni < 8; ni++) {
            int row = m0 + wm + mi * 16 + (lane >> 2);
            int col = n0 + wn + ni * 8 + (lane & 3) * 2;
            __half2 o0 = __floats2half2_rn(acc[mi][ni][0] * scale, acc[mi][ni][1] * scale);
            __half2 o1 = __floats2half2_rn(acc[mi][ni][2] * scale, acc[mi][ni][3] * scale);
            *(__half2*)(C + (size_t)row * SEQ + col)       = o0;
            *(__half2*)(C + (size_t)(row + 8) * SEQ + col) = o1;
        }
}

// ---------------- dual softmax (single max, bias via cexp identity) ----------------
__device__ __forceinline__ float warp_red_max(float v) {
#pragma unroll
    for (int o = 16; o; o >>= 1) v = fmaxf(v, __shfl_xor_sync(0xffffffffu, v, o));
    return v;
}
__device__ __forceinline__ float warp_red_sum(float v) {
#pragma unroll
    for (int o = 16; o; o >>= 1) v += __shfl_xor_sync(0xffffffffu, v, o);
    return v;
}

__global__ __launch_bounds__(256) void softmax_kernel(float* __restrict__ attn_w) {
    __shared__ float cexp_s[NHD][960];
    __shared__ float redA[8], redB[8];
    int blk = blockIdx.x;
    int b = blk >> 10, i = blk & 1023;
    int tid = threadIdx.x, w = tid >> 5, l = tid & 31;

    for (int t = tid; t < NHD * 960; t += 256)
        ((float*)cexp_s)[t] = g_cexp[t];

    ushort4 iv = *(const ushort4*)(g_idx + (size_t)i * SEQ + tid * 4);
    unsigned short idx4[4] = {iv.x, iv.y, iv.z, iv.w};
    float accw[4] = {0.f, 0.f, 0.f, 0.f};
    __syncthreads();

    for (int h = 0; h < NHD; h++) {
        __half* srow = g_sh + ((size_t)((b * NHD + h) * SEQ + i)) * SEQ;
        const __half2* sp = (const __half2*)(srow + tid * 4);
        float2 s01 = __half22float2(sp[0]);
        float2 s23 = __half22float2(sp[1]);
        float s[4] = {s01.x, s01.y, s23.x, s23.y};

        // block max of plain scores
        float m = fmaxf(fmaxf(s[0], s[1]), fmaxf(s[2], s[3]));
        m = warp_red_max(m);
        __syncthreads();
        if (l == 0) redA[w] = m;
        __syncthreads();
        m = redA[0];
#pragma unroll
        for (int k = 1; k < 8; k++) m = fmaxf(m, redA[k]);

        float E[4], cx[4], Zp = 0.f, Zb = 0.f;
#pragma unroll
        for (int t = 0; t < 4; t++) {
            E[t]  = __expf(s[t] - m);
            cx[t] = cexp_s[h][idx4[t]];
            Zp += E[t];
            Zb += E[t] * cx[t];
        }
        Zp = warp_red_sum(Zp);
        Zb = warp_red_sum(Zb);
        __syncthreads();
        if (l == 0) { redA[w] = Zp; redB[w] = Zb; }
        __syncthreads();
        Zp = redA[0]; Zb = redB[0];
#pragma unroll
        for (int k = 1; k < 8; k++) { Zp += redA[k]; Zb += redB[k]; }

        float ib = 1.0f / Zb, ip = 0.125f / Zp;
        __half2* op = (__half2*)(srow + tid * 4);
        op[0] = __floats2half2_rn(E[0] * cx[0] * ib, E[1] * cx[1] * ib);
        op[1] = __floats2half2_rn(E[2] * cx[2] * ib, E[3] * cx[3] * ib);
#pragma unroll
        for (int t = 0; t < 4; t++) accw[t] += E[t] * ip;
    }
    float4 wv4 = {accw[0], accw[1], accw[2], accw[3]};
    *(float4*)(attn_w + ((size_t)(b * SEQ + i)) * SEQ + tid * 4) = wv4;
}

// ---------------- ctx = probs @ v (tf32 mma, probs fp16 in gmem) ----------------
__global__ __launch_bounds__(256) void pv_kernel() {
    __shared__ __align__(16) float As[32][132];
    __shared__ __align__(16) float Vs[32][36];
    int bh = blockIdx.y;
    int b = bh >> 3, h = bh & 7;
    int m0 = blockIdx.x * 128;
    const __half* A = g_sh + (size_t)bh * SEQ * SEQ;
    const float* V = g_v + (size_t)b * SEQ * DMODEL + h * DKH;

    const int tid = threadIdx.x, lane = tid & 31, wid = tid >> 5;
    const int qr = lane >> 2, qc = lane & 3;
    float acc[4][4] = {};

    int vr = tid >> 3, vc = (tid & 7) * 4;

    for (int jt = 0; jt < SEQ; jt += 32) {
        load_tile_h(A, SEQ, m0, jt, As);
        float4 vv = *(const float4*)(V + (size_t)(jt + vr) * DMODEL + vc);
        Vs[vr][vc + 0] = vv.x; Vs[vr][vc + 1] = vv.y;
        Vs[vr][vc + 2] = vv.z; Vs[vr][vc + 3] = vv.w;
        __syncthreads();
#pragma unroll
        for (int kb = 0; kb < 32; kb += 8) {
            unsigned afr[4], bfr[4][2];
            int r = wid * 16 + qr;
            afr[0] = f2tf(As[kb + qc][r]);
            afr[1] = f2tf(As[kb + qc][r + 8]);
            afr[2] = f2tf(As[kb + 4 + qc][r]);
            afr[3] = f2tf(As[kb + 4 + qc][r + 8]);
#pragma unroll
            for (int ni = 0; ni < 4; ni++) {
                int nn = ni * 8 + qr;
                bfr[ni][0] = f2tf(Vs[kb + qc][nn]);
                bfr[ni][1] = f2tf(Vs[kb + 4 + qc][nn]);
            }
#pragma unroll
            for (int ni = 0; ni < 4; ni++)
                mma_tf32(acc[ni], afr, bfr[ni]);
        }
        __syncthreads();
    }

    int row = m0 + wid * 16 + qr;
    int col = qc * 2;
#pragma unroll
    for (int ni = 0; ni < 4; ni++) {
        float2 o0 = {acc[ni][0], acc[ni][1]};
        float2 o1 = {acc[ni][2], acc[ni][3]};
        *(float2*)(g_ctx + (size_t)(b * SEQ + row) * DMODEL + h * DKH + ni * 8 + col)     = o0;
        *(float2*)(g_ctx + (size_t)(b * SEQ + row + 8) * DMODEL + h * DKH + ni * 8 + col) = o1;
    }
}

// ---------------- out-proj + residual ----------------
__global__ __launch_bounds__(256) void outproj_kernel(
    const float* __restrict__ x, const float* __restrict__ wo, const float* __restrict__ bo)
{
    __shared__ __align__(16) float As[32][132];
    __shared__ __align__(16) float Bs[32][132];
    int m0 = blockIdx.y * 128, n0 = blockIdx.x * 128;
    float acc[2][8][4] = {};
    gemm_core_tf32(g_ctx, wo, DMODEL, DMODEL, m0, n0, DMODEL, acc, As, Bs);

    const int lane = threadIdx.x & 31, wid = threadIdx.x >> 5;
    const int wm = (wid & 3) * 32, wn = (wid >> 2) * 64;
#pragma unroll
    for (int mi = 0; mi < 2; mi++)
#pragma unroll
        for (int ni = 0; ni < 8; ni++) {
            int row = m0 + wm + mi * 16 + (lane >> 2);
            int col = n0 + wn + ni * 8 + (lane & 3) * 2;
            float2 bv = *(const float2*)(bo + col);
            float2 x0 = *(const float2*)(x + (size_t)row * DMODEL + col);
            float2 x1 = *(const float2*)(x + (size_t)(row + 8) * DMODEL + col);
            float2 o0 = {acc[mi][ni][0] + bv.x + x0.x, acc[mi][ni][1] + bv.y + x0.y};
            float2 o1 = {acc[mi][ni][2] + bv.x + x1.x, acc[mi][ni][3] + bv.y + x1.y};
            *(float2*)(g_tmp + (size_t)row * DMODEL + col)       = o0;
            *(float2*)(g_tmp + (size_t)(row + 8) * DMODEL + col) = o1;
        }
}

// ---------------- LayerNorm ----------------
__global__ __launch_bounds__(256) void ln_kernel(
    const float* __restrict__ lng, const float* __restrict__ lnb, float* __restrict__ y)
{
    __shared__ float red[8];
    size_t m = blockIdx.x;
    int tid = threadIdx.x, wd = tid >> 5, l = tid & 31;
    float v = g_tmp[m * DMODEL + tid];
    float s = warp_red_sum(v);
    if (l == 0) red[wd] = s;
    __syncthreads();
    float mu = 0.f;
#pragma unroll
    for (int k = 0; k < 8; k++) mu += red[k];
    mu *= (1.0f / DMODEL);
    __syncthreads();
    float d = v - mu;
    float sq = warp_red_sum(d * d);
    if (l == 0) red[wd] = sq;
    __syncthreads();
    float var = 0.f;
#pragma unroll
    for (int k = 0; k < 8; k++) var += red[k];
    var *= (1.0f / DMODEL);
    y[m * DMODEL + tid] = d * rsqrtf(var + 1e-5f) * lng[tid] + lnb[tid];
}

// ---------------- launch ----------------
extern "C" void kernel_launch(void* const* d_in, const int* in_sizes, int n_in,
                              void* d_out, int out_size) {
    const float* x    = (const float*)d_in[0];
    const float* wq   = (const float*)d_in[1];
    const float* bq   = (const float*)d_in[2];
    const float* wk   = (const float*)d_in[3];
    const float* bk   = (const float*)d_in[4];
    const float* wv   = (const float*)d_in[5];
    const float* bv   = (const float*)d_in[6];
    const float* wo   = (const float*)d_in[7];
    const float* bo   = (const float*)d_in[8];
    const float* lng  = (const float*)d_in[9];
    const float* lnb  = (const float*)d_in[10];
    const float* dist = (const float*)d_in[11];
    const float* dirb = (const float*)d_in[12];

    float* y_out  = (float*)d_out;
    float* aw_out = y_out + (size_t)BATCH * SEQ * DMODEL;

    comb_kernel<<<30, 256>>>(dist, dirb);
    idx_kernel<<<4096, 256>>>();
    proj_kernel<<<dim3(2, 64, 3), 256>>>(x, wq, wk, wv, bq, bk, bv);
    qk_kernel<<<dim3(8, 8, 64), 256>>>();
    softmax_kernel<<<8192, 256>>>(aw_out);
    pv_kernel<<<dim3(8, 64), 256>>>();
    outproj_kernel<<<dim3(2, 64, 1), 256>>>(x, wo, bo);
    ln_kernel<<<8192, 256>>>(lng, lnb, y_out);
}

// round 11
// speedup vs baseline: 1.9768x; 1.2440x over previous
#include <cuda_runtime.h>
#include <cuda_fp16.h>
#include <mma.h>

using namespace nvcuda;

#define BATCH  8
#define SEQ    1024
#define DMODEL 256
#define NHD    8
#define DKH    32

// ---------------- scratch (device globals; no allocations) ----------------
__device__ __half g_qh[(size_t)BATCH * SEQ * DMODEL];
__device__ __half g_kh[(size_t)BATCH * SEQ * DMODEL];
__device__ __half g_vh[(size_t)BATCH * SEQ * DMODEL];
__device__ __half g_sh[(size_t)BATCH * NHD * SEQ * SEQ];   // scores then probs, fp16 (134 MB)
__device__ float g_ctx[(size_t)BATCH * SEQ * DMODEL];
__device__ float g_tmp[(size_t)BATCH * SEQ * DMODEL];
__device__ unsigned short g_idx[SEQ * SEQ];
__device__ float g_cexp[NHD * 960];                        // exp(dist_bias + dir_bias)

// ---------------- tf32 mma helpers (proj / outproj keep fp32 inputs) ----------------
__device__ __forceinline__ unsigned f2tf(float f) {
    unsigned u;
    asm("cvt.rna.tf32.f32 %0, %1;" : "=r"(u) : "f"(f));
    return u;
}
__device__ __forceinline__ void mma_tf32(float* d, const unsigned* a, const unsigned* b) {
    asm volatile(
        "mma.sync.aligned.m16n8k8.row.col.f32.tf32.tf32.f32 "
        "{%0,%1,%2,%3}, {%4,%5,%6,%7}, {%8,%9}, {%0,%1,%2,%3};"
        : "+f"(d[0]), "+f"(d[1]), "+f"(d[2]), "+f"(d[3])
        : "r"(a[0]), "r"(a[1]), "r"(a[2]), "r"(a[3]), "r"(b[0]), "r"(b[1]));
}

// ---------------- bias-exp table + spatial index precompute ----------------
__global__ void comb_kernel(const float* __restrict__ dist_bias,
                            const float* __restrict__ dir_bias) {
    int t = blockIdx.x * 256 + threadIdx.x;
    if (t < NHD * 960) {
        int h = t / 960, r = t % 960;
        int di = r >> 4, dr = r & 15;
        g_cexp[t] = __expf(dist_bias[di * NHD + h] + dir_bias[dr * NHD + h]);
    }
}

__global__ void idx_kernel() {
    int e = blockIdx.x * 256 + threadIdx.x;
    int i = e >> 10, j = e & 1023;
    int h1 = i >> 5, w1 = i & 31, h2 = j >> 5, w2 = j & 31;
    int dh = h2 - h1, dw = w2 - w1;
    int n = dh * dh + dw * dw;
    int di = (int)sqrtf((float)n);
    if (di > 59) di = 59;
    int ex = -dw, ey = -dh, dir;
    if (ey == 0)            dir = (ex >= 0) ? 0 : 8;
    else if (ex == 0)       dir = (ey > 0) ? 4 : 12;
    else if (ex == ey)      dir = (ex > 0) ? 2 : 10;
    else if (ex == -ey)     dir = (ex > 0) ? 14 : 6;
    else {
        float a = atan2f((float)ey, (float)ex);
        if (a < 0.0f) a += 6.28318530717958647692f;
        dir = (int)(a * 2.54647908947032537164f);
        if (dir > 15) dir = 15;
    }
    g_idx[e] = (unsigned short)(di * 16 + dir);
}

// ---------------- fp32 smem tile loader for tf32 GEMMs ----------------
__device__ __forceinline__ void load_tile(const float* __restrict__ g, int ld,
                                          int r0, int kt, float (*S)[132]) {
    int lr = threadIdx.x >> 3, lc = (threadIdx.x & 7) * 4;
#pragma unroll
    for (int rr = 0; rr < 4; rr++) {
        int row = lr + rr * 32;
        float4 v = *(const float4*)(g + (size_t)(r0 + row) * ld + kt + lc);
        S[lc + 0][row] = v.x; S[lc + 1][row] = v.y;
        S[lc + 2][row] = v.z; S[lc + 3][row] = v.w;
    }
}

// ---------------- tf32 GEMM core: 128x128 tile, C = A(MxK) @ B(NxK)^T ----------------
__device__ __forceinline__ void gemm_core_tf32(
    const float* __restrict__ gA, const float* __restrict__ gB,
    int lda, int ldb, int m0, int n0, int K,
    float (&acc)[2][8][4], float (*As)[132], float (*Bs)[132])
{
    const int lane = threadIdx.x & 31, wid = threadIdx.x >> 5;
    const int wm = (wid & 3) * 32, wn = (wid >> 2) * 64;
    const int qr = lane >> 2, qc = lane & 3;

    for (int kt = 0; kt < K; kt += 32) {
        load_tile(gA, lda, m0, kt, As);
        load_tile(gB, ldb, n0, kt, Bs);
        __syncthreads();
#pragma unroll
        for (int kb = 0; kb < 32; kb += 8) {
            unsigned afr[2][4], bfr[8][2];
#pragma unroll
            for (int mi = 0; mi < 2; mi++) {
                int r = wm + mi * 16 + qr;
                afr[mi][0] = f2tf(As[kb + qc][r]);
                afr[mi][1] = f2tf(As[kb + qc][r + 8]);
                afr[mi][2] = f2tf(As[kb + 4 + qc][r]);
                afr[mi][3] = f2tf(As[kb + 4 + qc][r + 8]);
            }
#pragma unroll
            for (int ni = 0; ni < 8; ni++) {
                int nn = wn + ni * 8 + qr;
                bfr[ni][0] = f2tf(Bs[kb + qc][nn]);
                bfr[ni][1] = f2tf(Bs[kb + 4 + qc][nn]);
            }
#pragma unroll
            for (int mi = 0; mi < 2; mi++)
#pragma unroll
                for (int ni = 0; ni < 8; ni++)
                    mma_tf32(acc[mi][ni], afr[mi], bfr[ni]);
        }
        __syncthreads();
    }
}

// ---------------- QKV projection (tf32 compute, fp16 output) ----------------
__global__ __launch_bounds__(256) void proj_kernel(
    const float* __restrict__ x,
    const float* __restrict__ w0, const float* __restrict__ w1, const float* __restrict__ w2,
    const float* __restrict__ b0, const float* __restrict__ b1, const float* __restrict__ b2)
{
    __shared__ __align__(16) float As[32][132];
    __shared__ __align__(16) float Bs[32][132];
    int z = blockIdx.z;
    const float* W  = (z == 0) ? w0 : ((z == 1) ? w1 : w2);
    const float* bi = (z == 0) ? b0 : ((z == 1) ? b1 : b2);
    __half* out     = (z == 0) ? g_qh : ((z == 1) ? g_kh : g_vh);

    int m0 = blockIdx.y * 128, n0 = blockIdx.x * 128;
    float acc[2][8][4] = {};
    gemm_core_tf32(x, W, DMODEL, DMODEL, m0, n0, DMODEL, acc, As, Bs);

    const int lane = threadIdx.x & 31, wid = threadIdx.x >> 5;
    const int wm = (wid & 3) * 32, wn = (wid >> 2) * 64;
#pragma unroll
    for (int mi = 0; mi < 2; mi++)
#pragma unroll
        for (int ni = 0; ni < 8; ni++) {
            int row = m0 + wm + mi * 16 + (lane >> 2);
            int col = n0 + wn + ni * 8 + (lane & 3) * 2;
            float2 bv = *(const float2*)(bi + col);
            __half2 o0 = __floats2half2_rn(acc[mi][ni][0] + bv.x, acc[mi][ni][1] + bv.y);
            __half2 o1 = __floats2half2_rn(acc[mi][ni][2] + bv.x, acc[mi][ni][3] + bv.y);
            *(__half2*)(out + (size_t)row * DMODEL + col)       = o0;
            *(__half2*)(out + (size_t)(row + 8) * DMODEL + col) = o1;
        }
}

// ---------------- qk: scores = scale * q @ k^T (fp16 WMMA) ----------------
__global__ __launch_bounds__(256) void qk16_kernel() {
    __shared__ __align__(32) __half Qs[128][48];
    __shared__ __align__(32) __half Ks[128][48];
    __shared__ __align__(32) float buf[8][16][16];
    int bh = blockIdx.z;
    int b = bh >> 3, h = bh & 7;
    const __half* Q = g_qh + (size_t)b * SEQ * DMODEL + h * DKH;
    const __half* K = g_kh + (size_t)b * SEQ * DMODEL + h * DKH;
    __half* C = g_sh + (size_t)bh * SEQ * SEQ;

    int m0 = blockIdx.y * 128, n0 = blockIdx.x * 128;
    int tid = threadIdx.x;

#pragma unroll
    for (int it = 0; it < 2; it++) {
        int chunk = tid + it * 256;          // 0..511
        int row = chunk >> 2, off = (chunk & 3) * 8;
        *(uint4*)&Qs[row][off] = *(const uint4*)(Q + (size_t)(m0 + row) * DMODEL + off);
        *(uint4*)&Ks[row][off] = *(const uint4*)(K + (size_t)(n0 + row) * DMODEL + off);
    }
    __syncthreads();

    const int lane = tid & 31, wid = tid >> 5;
    const int wm = (wid & 3) * 32, wn = (wid >> 2) * 64;

    wmma::fragment<wmma::accumulator, 16, 16, 16, float> acc[2][4];
#pragma unroll
    for (int mi = 0; mi < 2; mi++)
#pragma unroll
        for (int ni = 0; ni < 4; ni++)
            wmma::fill_fragment(acc[mi][ni], 0.0f);

#pragma unroll
    for (int ks = 0; ks < 2; ks++) {
        wmma::fragment<wmma::matrix_a, 16, 16, 16, __half, wmma::row_major> af[2];
#pragma unroll
        for (int mi = 0; mi < 2; mi++)
            wmma::load_matrix_sync(af[mi], &Qs[wm + mi * 16][ks * 16], 48);
        wmma::fragment<wmma::matrix_b, 16, 16, 16, __half, wmma::col_major> bf[4];
#pragma unroll
        for (int ni = 0; ni < 4; ni++)
            wmma::load_matrix_sync(bf[ni], &Ks[wn + ni * 16][ks * 16], 48);
#pragma unroll
        for (int mi = 0; mi < 2; mi++)
#pragma unroll
            for (int ni = 0; ni < 4; ni++)
                wmma::mma_sync(acc[mi][ni], af[mi], bf[ni], acc[mi][ni]);
    }

    const float scale = 0.17677669529663688f;
    const int r = lane >> 1, cb = (lane & 1) * 8;
#pragma unroll
    for (int mi = 0; mi < 2; mi++)
#pragma unroll
        for (int ni = 0; ni < 4; ni++) {
#pragma unroll
            for (int e = 0; e < acc[mi][ni].num_elements; e++)
                acc[mi][ni].x[e] *= scale;
            wmma::store_matrix_sync(&buf[wid][0][0], acc[mi][ni], 16, wmma::mem_row_major);
            __syncwarp();
            const float* bp = &buf[wid][r][cb];
            __half2 hv[4];
#pragma unroll
            for (int e = 0; e < 4; e++)
                hv[e] = __floats2half2_rn(bp[2 * e], bp[2 * e + 1]);
            *(uint4*)(C + (size_t)(m0 + wm + mi * 16 + r) * SEQ + n0 + wn + ni * 16 + cb) =
                *(uint4*)hv;
            __syncwarp();
        }
}

// ---------------- dual softmax (single max, bias via cexp identity) ----------------
__device__ __forceinline__ float warp_red_max(float v) {
#pragma unroll
    for (int o = 16; o; o >>= 1) v = fmaxf(v, __shfl_xor_sync(0xffffffffu, v, o));
    return v;
}
__device__ __forceinline__ float warp_red_sum(float v) {
#pragma unroll
    for (int o = 16; o; o >>= 1) v += __shfl_xor_sync(0xffffffffu, v, o);
    return v;
}

__global__ __launch_bounds__(256) void softmax_kernel(float* __restrict__ attn_w) {
    __shared__ float cexp_s[NHD][960];
    __shared__ float redA[8], redB[8];
    int blk = blockIdx.x;
    int b = blk >> 10, i = blk & 1023;
    int tid = threadIdx.x, w = tid >> 5, l = tid & 31;

    for (int t = tid; t < NHD * 960; t += 256)
        ((float*)cexp_s)[t] = g_cexp[t];

    ushort4 iv = *(const ushort4*)(g_idx + (size_t)i * SEQ + tid * 4);
    unsigned short idx4[4] = {iv.x, iv.y, iv.z, iv.w};
    float accw[4] = {0.f, 0.f, 0.f, 0.f};
    __syncthreads();

    for (int h = 0; h < NHD; h++) {
        __half* srow = g_sh + ((size_t)((b * NHD + h) * SEQ + i)) * SEQ;
        const __half2* sp = (const __half2*)(srow + tid * 4);
        float2 s01 = __half22float2(sp[0]);
        float2 s23 = __half22float2(sp[1]);
        float s[4] = {s01.x, s01.y, s23.x, s23.y};

        float m = fmaxf(fmaxf(s[0], s[1]), fmaxf(s[2], s[3]));
        m = warp_red_max(m);
        __syncthreads();
        if (l == 0) redA[w] = m;
        __syncthreads();
        m = redA[0];
#pragma unroll
        for (int k = 1; k < 8; k++) m = fmaxf(m, redA[k]);

        float E[4], cx[4], Zp = 0.f, Zb = 0.f;
#pragma unroll
        for (int t = 0; t < 4; t++) {
            E[t]  = __expf(s[t] - m);
            cx[t] = cexp_s[h][idx4[t]];
            Zp += E[t];
            Zb += E[t] * cx[t];
        }
        Zp = warp_red_sum(Zp);
        Zb = warp_red_sum(Zb);
        __syncthreads();
        if (l == 0) { redA[w] = Zp; redB[w] = Zb; }
        __syncthreads();
        Zp = redA[0]; Zb = redB[0];
#pragma unroll
        for (int k = 1; k < 8; k++) { Zp += redA[k]; Zb += redB[k]; }

        float ib = 1.0f / Zb, ip = 0.125f / Zp;
        __half2* op = (__half2*)(srow + tid * 4);
        op[0] = __floats2half2_rn(E[0] * cx[0] * ib, E[1] * cx[1] * ib);
        op[1] = __floats2half2_rn(E[2] * cx[2] * ib, E[3] * cx[3] * ib);
#pragma unroll
        for (int t = 0; t < 4; t++) accw[t] += E[t] * ip;
    }
    float4 wv4 = {accw[0], accw[1], accw[2], accw[3]};
    *(float4*)(attn_w + ((size_t)(b * SEQ + i)) * SEQ + tid * 4) = wv4;
}

// ---------------- ctx = probs @ v (fp16 WMMA) ----------------
__global__ __launch_bounds__(256) void pv16_kernel() {
    __shared__ __align__(32) __half Ps[128][80];
    __shared__ __align__(32) __half Vs[64][48];
    int bh = blockIdx.y;
    int b = bh >> 3, h = bh & 7;
    int m0 = blockIdx.x * 128;
    const __half* P = g_sh + (size_t)bh * SEQ * SEQ;
    const __half* V = g_vh + (size_t)b * SEQ * DMODEL + h * DKH;

    const int tid = threadIdx.x, wid = tid >> 5;
    const int wm = wid * 16;

    wmma::fragment<wmma::accumulator, 16, 16, 16, float> acc[2];
    wmma::fill_fragment(acc[0], 0.0f);
    wmma::fill_fragment(acc[1], 0.0f);

    for (int jt = 0; jt < SEQ; jt += 64) {
#pragma unroll
        for (int it = 0; it < 4; it++) {
            int chunk = tid + it * 256;     // 0..1023
            int row = chunk >> 3, off = (chunk & 7) * 8;
            *(uint4*)&Ps[row][off] = *(const uint4*)(P + (size_t)(m0 + row) * SEQ + jt + off);
        }
        {
            int row = tid >> 2, off = (tid & 3) * 8;
            *(uint4*)&Vs[row][off] = *(const uint4*)(V + (size_t)(jt + row) * DMODEL + off);
        }
        __syncthreads();

#pragma unroll
        for (int ks = 0; ks < 4; ks++) {
            wmma::fragment<wmma::matrix_a, 16, 16, 16, __half, wmma::row_major> af;
            wmma::load_matrix_sync(af, &Ps[wm][ks * 16], 80);
            wmma::fragment<wmma::matrix_b, 16, 16, 16, __half, wmma::row_major> bf[2];
            wmma::load_matrix_sync(bf[0], &Vs[ks * 16][0], 48);
            wmma::load_matrix_sync(bf[1], &Vs[ks * 16][16], 48);
            wmma::mma_sync(acc[0], af, bf[0], acc[0]);
            wmma::mma_sync(acc[1], af, bf[1], acc[1]);
        }
        __syncthreads();
    }

    float* out = g_ctx + ((size_t)(b * SEQ + m0 + wm)) * DMODEL + h * DKH;
    wmma::store_matrix_sync(out,      acc[0], DMODEL, wmma::mem_row_major);
    wmma::store_matrix_sync(out + 16, acc[1], DMODEL, wmma::mem_row_major);
}

// ---------------- out-proj + residual (tf32) ----------------
__global__ __launch_bounds__(256) void outproj_kernel(
    const float* __restrict__ x, const float* __restrict__ wo, const float* __restrict__ bo)
{
    __shared__ __align__(16) float As[32][132];
    __shared__ __align__(16) float Bs[32][132];
    int m0 = blockIdx.y * 128, n0 = blockIdx.x * 128;
    float acc[2][8][4] = {};
    gemm_core_tf32(g_ctx, wo, DMODEL, DMODEL, m0, n0, DMODEL, acc, As, Bs);

    const int lane = threadIdx.x & 31, wid = threadIdx.x >> 5;
    const int wm = (wid & 3) * 32, wn = (wid >> 2) * 64;
#pragma unroll
    for (int mi = 0; mi < 2; mi++)
#pragma unroll
        for (int ni = 0; ni < 8; ni++) {
            int row = m0 + wm + mi * 16 + (lane >> 2);
            int col = n0 + wn + ni * 8 + (lane & 3) * 2;
            float2 bv = *(const float2*)(bo + col);
            float2 x0 = *(const float2*)(x + (size_t)row * DMODEL + col);
            float2 x1 = *(const float2*)(x + (size_t)(row + 8) * DMODEL + col);
            float2 o0 = {acc[mi][ni][0] + bv.x + x0.x, acc[mi][ni][1] + bv.y + x0.y};
            float2 o1 = {acc[mi][ni][2] + bv.x + x1.x, acc[mi][ni][3] + bv.y + x1.y};
            *(float2*)(g_tmp + (size_t)row * DMODEL + col)       = o0;
            *(float2*)(g_tmp + (size_t)(row + 8) * DMODEL + col) = o1;
        }
}

// ---------------- LayerNorm ----------------
__global__ __launch_bounds__(256) void ln_kernel(
    const float* __restrict__ lng, const float* __restrict__ lnb, float* __restrict__ y)
{
    __shared__ float red[8];
    size_t m = blockIdx.x;
    int tid = threadIdx.x, wd = tid >> 5, l = tid & 31;
    float v = g_tmp[m * DMODEL + tid];
    float s = warp_red_sum(v);
    if (l == 0) red[wd] = s;
    __syncthreads();
    float mu = 0.f;
#pragma unroll
    for (int k = 0; k < 8; k++) mu += red[k];
    mu *= (1.0f / DMODEL);
    __syncthreads();
    float d = v - mu;
    float sq = warp_red_sum(d * d);
    if (l == 0) red[wd] = sq;
    __syncthreads();
    float var = 0.f;
#pragma unroll
    for (int k = 0; k < 8; k++) var += red[k];
    var *= (1.0f / DMODEL);
    y[m * DMODEL + tid] = d * rsqrtf(var + 1e-5f) * lng[tid] + lnb[tid];
}

// ---------------- launch ----------------
extern "C" void kernel_launch(void* const* d_in, const int* in_sizes, int n_in,
                              void* d_out, int out_size) {
    const float* x    = (const float*)d_in[0];
    const float* wq   = (const float*)d_in[1];
    const float* bq   = (const float*)d_in[2];
    const float* wk   = (const float*)d_in[3];
    const float* bk   = (const float*)d_in[4];
    const float* wv   = (const float*)d_in[5];
    const float* bv   = (const float*)d_in[6];
    const float* wo   = (const float*)d_in[7];
    const float* bo   = (const float*)d_in[8];
    const float* lng  = (const float*)d_in[9];
    const float* lnb  = (const float*)d_in[10];
    const float* dist = (const float*)d_in[11];
    const float* dirb = (const float*)d_in[12];

    float* y_out  = (float*)d_out;
    float* aw_out = y_out + (size_t)BATCH * SEQ * DMODEL;

    comb_kernel<<<30, 256>>>(dist, dirb);
    idx_kernel<<<4096, 256>>>();
    proj_kernel<<<dim3(2, 64, 3), 256>>>(x, wq, wk, wv, bq, bk, bv);
    qk16_kernel<<<dim3(8, 8, 64), 256>>>();
    softmax_kernel<<<8192, 256>>>(aw_out);
    pv16_kernel<<<dim3(8, 64), 256>>>();
    outproj_kernel<<<dim3(2, 64, 1), 256>>>(x, wo, bo);
    ln_kernel<<<8192, 256>>>(lng, lnb, y_out);
}

// round 14
// speedup vs baseline: 2.4024x; 1.2153x over previous
#include <cuda_runtime.h>
#include <cuda_fp16.h>
#include <mma.h>

using namespace nvcuda;

#define BATCH  8
#define SEQ    1024
#define DMODEL 256
#define NHD    8
#define DKH    32

// ---------------- scratch (device globals; no allocations) ----------------
__device__ __half g_xh[(size_t)BATCH * SEQ * DMODEL];
__device__ __half g_wqh[DMODEL * DMODEL];
__device__ __half g_wkh[DMODEL * DMODEL];
__device__ __half g_wvh[DMODEL * DMODEL];
__device__ __half g_woh[DMODEL * DMODEL];
__device__ __half g_qh[(size_t)BATCH * SEQ * DMODEL];
__device__ __half g_kh[(size_t)BATCH * SEQ * DMODEL];
__device__ __half g_vh[(size_t)BATCH * SEQ * DMODEL];
__device__ __half g_sh[(size_t)BATCH * NHD * SEQ * SEQ];   // scores then probs (134 MB)
__device__ __half g_ctxh[(size_t)BATCH * SEQ * DMODEL];
__device__ float g_tmp[(size_t)BATCH * SEQ * DMODEL];
__device__ unsigned short g_idx[SEQ * SEQ];
__device__ float g_cexp[NHD * 960];                        // exp(dist_bias + dir_bias)

// ---------------- fp32 -> fp16 conversion (x, wq, wk, wv, wo) ----------------
#define NX (BATCH * SEQ * DMODEL)
#define NW (DMODEL * DMODEL)
__global__ void conv_kernel(const float* __restrict__ x,
                            const float* __restrict__ wq, const float* __restrict__ wk,
                            const float* __restrict__ wv, const float* __restrict__ wo) {
    int i4 = (blockIdx.x * 256 + threadIdx.x) * 4;
    const float* src; __half* dst; int off;
    if (i4 < NX)               { src = x;  dst = g_xh;  off = i4; }
    else if (i4 < NX + NW)     { src = wq; dst = g_wqh; off = i4 - NX; }
    else if (i4 < NX + 2 * NW) { src = wk; dst = g_wkh; off = i4 - NX - NW; }
    else if (i4 < NX + 3 * NW) { src = wv; dst = g_wvh; off = i4 - NX - 2 * NW; }
    else                       { src = wo; dst = g_woh; off = i4 - NX - 3 * NW; }
    float4 v = *(const float4*)(src + off);
    __half2 h01 = __floats2half2_rn(v.x, v.y);
    __half2 h23 = __floats2half2_rn(v.z, v.w);
    __half2 hv[2] = {h01, h23};
    *(uint2*)(dst + off) = *(uint2*)hv;
}

// ---------------- bias-exp table + spatial index precompute ----------------
__global__ void comb_kernel(const float* __restrict__ dist_bias,
                            const float* __restrict__ dir_bias) {
    int t = blockIdx.x * 256 + threadIdx.x;
    if (t < NHD * 960) {
        int h = t / 960, r = t % 960;
        int di = r >> 4, dr = r & 15;
        g_cexp[t] = __expf(dist_bias[di * NHD + h] + dir_bias[dr * NHD + h]);
    }
}

__global__ void idx_kernel() {
    int e = blockIdx.x * 256 + threadIdx.x;
    int i = e >> 10, j = e & 1023;
    int h1 = i >> 5, w1 = i & 31, h2 = j >> 5, w2 = j & 31;
    int dh = h2 - h1, dw = w2 - w1;
    int n = dh * dh + dw * dw;
    int di = (int)sqrtf((float)n);
    if (di > 59) di = 59;
    int ex = -dw, ey = -dh, dir;
    if (ey == 0)            dir = (ex >= 0) ? 0 : 8;
    else if (ex == 0)       dir = (ey > 0) ? 4 : 12;
    else if (ex == ey)      dir = (ex > 0) ? 2 : 10;
    else if (ex == -ey)     dir = (ex > 0) ? 14 : 6;
    else {
        float a = atan2f((float)ey, (float)ex);
        if (a < 0.0f) a += 6.28318530717958647692f;
        dir = (int)(a * 2.54647908947032537164f);
        if (dir > 15) dir = 15;
    }
    g_idx[e] = (unsigned short)(di * 16 + dir);
}

// ---------------- warp epilogue: f32 accum fragment -> fp16 gmem tile ----------------
template <bool BIAS>
__device__ __forceinline__ void frag_to_half(
    wmma::fragment<wmma::accumulator, 16, 16, 16, float>& acc,
    float (*buf)[20], __half* gp, int ldg, float mult, const float* bias)
{
    wmma::store_matrix_sync(&buf[0][0], acc, 20, wmma::mem_row_major);
    __syncwarp();
    int lane = threadIdx.x & 31;
    int r = lane >> 1, c = (lane & 1) * 8;
    const float* bp = &buf[r][c];
    __half2 hv[4];
#pragma unroll
    for (int j = 0; j < 4; j++) {
        float v0 = bp[2 * j] * mult, v1 = bp[2 * j + 1] * mult;
        if (BIAS) { v0 += bias[c + 2 * j]; v1 += bias[c + 2 * j + 1]; }
        hv[j] = __floats2half2_rn(v0, v1);
    }
    *(uint4*)(gp + (size_t)r * ldg + c) = *(uint4*)hv;
    __syncwarp();
}

// ---------------- fp16 NT GEMM 128x128, K=256: out(fp16) = A @ B^T + bias ----------------
__global__ __launch_bounds__(256) void proj16_kernel() {
    __shared__ __align__(32) __half As[128][72];
    __shared__ __align__(32) __half Bs[128][72];
    __shared__ __align__(32) float buf[8][16][20];
    int z = blockIdx.z;
    const __half* A = g_xh;
    const __half* B = (z == 0) ? g_wqh : ((z == 1) ? g_wkh : g_wvh);
    __half* out     = (z == 0) ? g_qh  : ((z == 1) ? g_kh  : g_vh);

    int m0 = blockIdx.y * 128, n0 = blockIdx.x * 128;
    int tid = threadIdx.x;
    const int wid = tid >> 5;
    const int wm = (wid & 3) * 32, wn = (wid >> 2) * 64;

    wmma::fragment<wmma::accumulator, 16, 16, 16, float> acc[2][4];
#pragma unroll
    for (int mi = 0; mi < 2; mi++)
#pragma unroll
        for (int ni = 0; ni < 4; ni++) wmma::fill_fragment(acc[mi][ni], 0.0f);

    for (int kt = 0; kt < DMODEL; kt += 64) {
#pragma unroll
        for (int it = 0; it < 4; it++) {
            int chunk = tid + it * 256;       // 0..1023
            int row = chunk >> 3, off = (chunk & 7) * 8;
            *(uint4*)&As[row][off] = *(const uint4*)(A + (size_t)(m0 + row) * DMODEL + kt + off);
            *(uint4*)&Bs[row][off] = *(const uint4*)(B + (size_t)(n0 + row) * DMODEL + kt + off);
        }
        __syncthreads();
#pragma unroll
        for (int ks = 0; ks < 4; ks++) {
            wmma::fragment<wmma::matrix_a, 16, 16, 16, __half, wmma::row_major> af[2];
#pragma unroll
            for (int mi = 0; mi < 2; mi++)
                wmma::load_matrix_sync(af[mi], &As[wm + mi * 16][ks * 16], 72);
            wmma::fragment<wmma::matrix_b, 16, 16, 16, __half, wmma::col_major> bf[4];
#pragma unroll
            for (int ni = 0; ni < 4; ni++)
                wmma::load_matrix_sync(bf[ni], &Bs[wn + ni * 16][ks * 16], 72);
#pragma unroll
            for (int mi = 0; mi < 2; mi++)
#pragma unroll
                for (int ni = 0; ni < 4; ni++)
                    wmma::mma_sync(acc[mi][ni], af[mi], bf[ni], acc[mi][ni]);
        }
        __syncthreads();
    }
    // bias pointers passed via constant globals would be cleaner; fetch via param below
    extern __shared__ int _dummy[];
    const float* bi = (const float*)0;  // patched by wrapper: use param kernel instead
    (void)bi;
    // epilogue with bias is handled in launch wrapper variant
    // (this kernel is replaced by proj16b below)
}

// proj with bias as parameter (the one actually launched)
__global__ __launch_bounds__(256) void proj16b_kernel(
    const float* __restrict__ b0, const float* __restrict__ b1, const float* __restrict__ b2)
{
    __shared__ __align__(32) __half As[128][72];
    __shared__ __align__(32) __half Bs[128][72];
    __shared__ __align__(32) float buf[8][16][20];
    int z = blockIdx.z;
    const __half* A = g_xh;
    const __half* B = (z == 0) ? g_wqh : ((z == 1) ? g_wkh : g_wvh);
    const float* bi = (z == 0) ? b0 : ((z == 1) ? b1 : b2);
    __half* out     = (z == 0) ? g_qh  : ((z == 1) ? g_kh  : g_vh);

    int m0 = blockIdx.y * 128, n0 = blockIdx.x * 128;
    int tid = threadIdx.x;
    const int wid = tid >> 5;
    const int wm = (wid & 3) * 32, wn = (wid >> 2) * 64;

    wmma::fragment<wmma::accumulator, 16, 16, 16, float> acc[2][4];
#pragma unroll
    for (int mi = 0; mi < 2; mi++)
#pragma unroll
        for (int ni = 0; ni < 4; ni++) wmma::fill_fragment(acc[mi][ni], 0.0f);

    for (int kt = 0; kt < DMODEL; kt += 64) {
#pragma unroll
        for (int it = 0; it < 4; it++) {
            int chunk = tid + it * 256;
            int row = chunk >> 3, off = (chunk & 7) * 8;
            *(uint4*)&As[row][off] = *(const uint4*)(A + (size_t)(m0 + row) * DMODEL + kt + off);
            *(uint4*)&Bs[row][off] = *(const uint4*)(B + (size_t)(n0 + row) * DMODEL + kt + off);
        }
        __syncthreads();
#pragma unroll
        for (int ks = 0; ks < 4; ks++) {
            wmma::fragment<wmma::matrix_a, 16, 16, 16, __half, wmma::row_major> af[2];
#pragma unroll
            for (int mi = 0; mi < 2; mi++)
                wmma::load_matrix_sync(af[mi], &As[wm + mi * 16][ks * 16], 72);
            wmma::fragment<wmma::matrix_b, 16, 16, 16, __half, wmma::col_major> bf[4];
#pragma unroll
            for (int ni = 0; ni < 4; ni++)
                wmma::load_matrix_sync(bf[ni], &Bs[wn + ni * 16][ks * 16], 72);
#pragma unroll
            for (int mi = 0; mi < 2; mi++)
#pragma unroll
                for (int ni = 0; ni < 4; ni++)
                    wmma::mma_sync(acc[mi][ni], af[mi], bf[ni], acc[mi][ni]);
        }
        __syncthreads();
    }
#pragma unroll
    for (int mi = 0; mi < 2; mi++)
#pragma unroll
        for (int ni = 0; ni < 4; ni++)
            frag_to_half<true>(acc[mi][ni], buf[wid],
                out + (size_t)(m0 + wm + mi * 16) * DMODEL + n0 + wn + ni * 16,
                DMODEL, 1.0f, bi + n0 + wn + ni * 16);
}

// ---------------- qk: scores = scale * q @ k^T ----------------
__global__ __launch_bounds__(256) void qk16_kernel() {
    __shared__ __align__(32) __half Qs[128][40];
    __shared__ __align__(32) __half Ks[128][40];
    __shared__ __align__(32) float buf[8][16][20];
    int bh = blockIdx.z;
    int b = bh >> 3, h = bh & 7;
    const __half* Q = g_qh + (size_t)b * SEQ * DMODEL + h * DKH;
    const __half* K = g_kh + (size_t)b * SEQ * DMODEL + h * DKH;
    __half* C = g_sh + (size_t)bh * SEQ * SEQ;

    int m0 = blockIdx.y * 128, n0 = blockIdx.x * 128;
    int tid = threadIdx.x;

#pragma unroll
    for (int it = 0; it < 2; it++) {
        int chunk = tid + it * 256;
        int row = chunk >> 2, off = (chunk & 3) * 8;
        *(uint4*)&Qs[row][off] = *(const uint4*)(Q + (size_t)(m0 + row) * DMODEL + off);
        *(uint4*)&Ks[row][off] = *(const uint4*)(K + (size_t)(n0 + row) * DMODEL + off);
    }
    __syncthreads();

    const int wid = tid >> 5;
    const int wm = (wid & 3) * 32, wn = (wid >> 2) * 64;

    wmma::fragment<wmma::accumulator, 16, 16, 16, float> acc[2][4];
#pragma unroll
    for (int mi = 0; mi < 2; mi++)
#pragma unroll
        for (int ni = 0; ni < 4; ni++) wmma::fill_fragment(acc[mi][ni], 0.0f);

#pragma unroll
    for (int ks = 0; ks < 2; ks++) {
        wmma::fragment<wmma::matrix_a, 16, 16, 16, __half, wmma::row_major> af[2];
#pragma unroll
        for (int mi = 0; mi < 2; mi++)
            wmma::load_matrix_sync(af[mi], &Qs[wm + mi * 16][ks * 16], 40);
        wmma::fragment<wmma::matrix_b, 16, 16, 16, __half, wmma::col_major> bf[4];
#pragma unroll
        for (int ni = 0; ni < 4; ni++)
            wmma::load_matrix_sync(bf[ni], &Ks[wn + ni * 16][ks * 16], 40);
#pragma unroll
        for (int mi = 0; mi < 2; mi++)
#pragma unroll
            for (int ni = 0; ni < 4; ni++)
                wmma::mma_sync(acc[mi][ni], af[mi], bf[ni], acc[mi][ni]);
    }

    const float scale = 0.17677669529663688f;
#pragma unroll
    for (int mi = 0; mi < 2; mi++)
#pragma unroll
        for (int ni = 0; ni < 4; ni++)
            frag_to_half<false>(acc[mi][ni], buf[wid],
                C + (size_t)(m0 + wm + mi * 16) * SEQ + n0 + wn + ni * 16,
                SEQ, scale, nullptr);
}

// ---------------- dual softmax: warp per (b,i) row across 8 heads; m=0 (safe) ----------------
__global__ __launch_bounds__(256) void softmax_kernel(float* __restrict__ attn_w) {
    __shared__ float cexp_s[NHD][960];
    int blk = blockIdx.x;                    // 0..1023
    int b = blk >> 7, i0 = (blk & 127) * 8;
    int tid = threadIdx.x, w = tid >> 5, l = tid & 31;
    int i = i0 + w;

    for (int t = tid; t < NHD * 960; t += 256)
        ((float*)cexp_s)[t] = g_cexp[t];
    __syncthreads();

    float aw[32];
#pragma unroll
    for (int e = 0; e < 32; e++) aw[e] = 0.f;

    const int c0 = l * 32;

    for (int h = 0; h < NHD; h++) {
        __half* srow = g_sh + ((size_t)((b * NHD + h) * SEQ + i)) * SEQ + c0;
        const unsigned short* irow = g_idx + (size_t)i * SEQ + c0;

        uint4 raw[4];
#pragma unroll
        for (int t = 0; t < 4; t++) raw[t] = ((const uint4*)srow)[t];
        uint4 iraw[4];
#pragma unroll
        for (int t = 0; t < 4; t++) iraw[t] = ((const uint4*)irow)[t];
        const unsigned short* idx = (const unsigned short*)iraw;
        const __half2* sh2 = (const __half2*)raw;

        float E[32], Eb[32];
        float Zp = 0.f, Zb = 0.f;
#pragma unroll
        for (int t = 0; t < 16; t++) {
            float2 f = __half22float2(sh2[t]);
            E[2 * t]     = __expf(f.x);
            E[2 * t + 1] = __expf(f.y);
        }
#pragma unroll
        for (int e = 0; e < 32; e++) {
            Eb[e] = E[e] * cexp_s[h][idx[e]];
            Zp += E[e];
            Zb += Eb[e];
        }
#pragma unroll
        for (int o = 16; o; o >>= 1) {
            Zp += __shfl_xor_sync(0xffffffffu, Zp, o);
            Zb += __shfl_xor_sync(0xffffffffu, Zb, o);
        }
        float ib = 1.0f / Zb, ipw = 0.125f / Zp;

        __half2 hv[16];
#pragma unroll
        for (int t = 0; t < 16; t++)
            hv[t] = __floats2half2_rn(Eb[2 * t] * ib, Eb[2 * t + 1] * ib);
#pragma unroll
        for (int t = 0; t < 4; t++) ((uint4*)srow)[t] = ((uint4*)hv)[t];

#pragma unroll
        for (int e = 0; e < 32; e++) aw[e] += E[e] * ipw;
    }

    float* awp = attn_w + ((size_t)(b * SEQ + i)) * SEQ + c0;
#pragma unroll
    for (int t = 0; t < 8; t++)
        ((float4*)awp)[t] = ((float4*)aw)[t];
}

// ---------------- ctx = probs @ v -> fp16 ctx ----------------
__global__ __launch_bounds__(256) void pv16_kernel() {
    __shared__ __align__(32) __half Ps[128][72];
    __shared__ __align__(32) __half Vs[64][40];
    __shared__ __align__(32) float buf[8][16][20];
    int bh = blockIdx.y;
    int b = bh >> 3, h = bh & 7;
    int m0 = blockIdx.x * 128;
    const __half* P = g_sh + (size_t)bh * SEQ * SEQ;
    const __half* V = g_vh + (size_t)b * SEQ * DMODEL + h * DKH;

    const int tid = threadIdx.x, wid = tid >> 5;
    const int wm = wid * 16;

    wmma::fragment<wmma::accumulator, 16, 16, 16, float> acc[2];
    wmma::fill_fragment(acc[0], 0.0f);
    wmma::fill_fragment(acc[1], 0.0f);

    for (int jt = 0; jt < SEQ; jt += 64) {
#pragma unroll
        for (int it = 0; it < 4; it++) {
            int chunk = tid + it * 256;
            int row = chunk >> 3, off = (chunk & 7) * 8;
            *(uint4*)&Ps[row][off] = *(const uint4*)(P + (size_t)(m0 + row) * SEQ + jt + off);
        }
        {
            int row = tid >> 2, off = (tid & 3) * 8;
            *(uint4*)&Vs[row][off] = *(const uint4*)(V + (size_t)(jt + row) * DMODEL + off);
        }
        __syncthreads();

#pragma unroll
        for (int ks = 0; ks < 4; ks++) {
            wmma::fragment<wmma::matrix_a, 16, 16, 16, __half, wmma::row_major> af;
            wmma::load_matrix_sync(af, &Ps[wm][ks * 16], 72);
            wmma::fragment<wmma::matrix_b, 16, 16, 16, __half, wmma::row_major> bf[2];
            wmma::load_matrix_sync(bf[0], &Vs[ks * 16][0], 40);
            wmma::load_matrix_sync(bf[1], &Vs[ks * 16][16], 40);
            wmma::mma_sync(acc[0], af, bf[0], acc[0]);
            wmma::mma_sync(acc[1], af, bf[1], acc[1]);
        }
        __syncthreads();
    }

    __half* out = g_ctxh + ((size_t)(b * SEQ + m0 + wm)) * DMODEL + h * DKH;
    frag_to_half<false>(acc[0], buf[wid], out,      DMODEL, 1.0f, nullptr);
    frag_to_half<false>(acc[1], buf[wid], out + 16, DMODEL, 1.0f, nullptr);
}

// ---------------- out-proj: tmp = ctx @ wo^T (f32 out; bias+residual in ln) ----------------
__global__ __launch_bounds__(256) void outproj16_kernel() {
    __shared__ __align__(32) __half As[128][72];
    __shared__ __align__(32) __half Bs[128][72];
    int m0 = blockIdx.y * 128, n0 = blockIdx.x * 128;
    int tid = threadIdx.x;
    const int wid = tid >> 5;
    const int wm = (wid & 3) * 32, wn = (wid >> 2) * 64;

    wmma::fragment<wmma::accumulator, 16, 16, 16, float> acc[2][4];
#pragma unroll
    for (int mi = 0; mi < 2; mi++)
#pragma unroll
        for (int ni = 0; ni < 4; ni++) wmma::fill_fragment(acc[mi][ni], 0.0f);

    for (int kt = 0; kt < DMODEL; kt += 64) {
#pragma unroll
        for (int it = 0; it < 4; it++) {
            int chunk = tid + it * 256;
            int row = chunk >> 3, off = (chunk & 7) * 8;
            *(uint4*)&As[row][off] = *(const uint4*)(g_ctxh + (size_t)(m0 + row) * DMODEL + kt + off);
            *(uint4*)&Bs[row][off] = *(const uint4*)(g_woh  + (size_t)(n0 + row) * DMODEL + kt + off);
        }
        __syncthreads();
#pragma unroll
        for (int ks = 0; ks < 4; ks++) {
            wmma::fragment<wmma::matrix_a, 16, 16, 16, __half, wmma::row_major> af[2];
#pragma unroll
            for (int mi = 0; mi < 2; mi++)
                wmma::load_matrix_sync(af[mi], &As[wm + mi * 16][ks * 16], 72);
            wmma::fragment<wmma::matrix_b, 16, 16, 16, __half, wmma::col_major> bf[4];
#pragma unroll
            for (int ni = 0; ni < 4; ni++)
                wmma::load_matrix_sync(bf[ni], &Bs[wn + ni * 16][ks * 16], 72);
#pragma unroll
            for (int mi = 0; mi < 2; mi++)
#pragma unroll
                for (int ni = 0; ni < 4; ni++)
                    wmma::mma_sync(acc[mi][ni], af[mi], bf[ni], acc[mi][ni]);
        }
        __syncthreads();
    }
#pragma unroll
    for (int mi = 0; mi < 2; mi++)
#pragma unroll
        for (int ni = 0; ni < 4; ni++)
            wmma::store_matrix_sync(
                g_tmp + (size_t)(m0 + wm + mi * 16) * DMODEL + n0 + wn + ni * 16,
                acc[mi][ni], DMODEL, wmma::mem_row_major);
}

// ---------------- LayerNorm (adds out-proj bias + residual) ----------------
__device__ __forceinline__ float warp_red_sum(float v) {
#pragma unroll
    for (int o = 16; o; o >>= 1) v += __shfl_xor_sync(0xffffffffu, v, o);
    return v;
}
__global__ __launch_bounds__(256) void ln_kernel(
    const float* __restrict__ x, const float* __restrict__ bo,
    const float* __restrict__ lng, const float* __restrict__ lnb, float* __restrict__ y)
{
    __shared__ float red[8];
    size_t m = blockIdx.x;
    int tid = threadIdx.x, wd = tid >> 5, l = tid & 31;
    float v = g_tmp[m * DMODEL + tid] + bo[tid] + x[m * DMODEL + tid];
    float s = warp_red_sum(v);
    if (l == 0) red[wd] = s;
    __syncthreads();
    float mu = 0.f;
#pragma unroll
    for (int k = 0; k < 8; k++) mu += red[k];
    mu *= (1.0f / DMODEL);
    __syncthreads();
    float d = v - mu;
    float sq = warp_red_sum(d * d);
    if (l == 0) red[wd] = sq;
    __syncthreads();
    float var = 0.f;
#pragma unroll
    for (int k = 0; k < 8; k++) var += red[k];
    var *= (1.0f / DMODEL);
    y[m * DMODEL + tid] = d * rsqrtf(var + 1e-5f) * lng[tid] + lnb[tid];
}

// ---------------- launch ----------------
extern "C" void kernel_launch(void* const* d_in, const int* in_sizes, int n_in,
                              void* d_out, int out_size) {
    const float* x    = (const float*)d_in[0];
    const float* wq   = (const float*)d_in[1];
    const float* bq   = (const float*)d_in[2];
    const float* wk   = (const float*)d_in[3];
    const float* bk   = (const float*)d_in[4];
    const float* wv   = (const float*)d_in[5];
    const float* bv   = (const float*)d_in[6];
    const float* wo   = (const float*)d_in[7];
    const float* bo   = (const float*)d_in[8];
    const float* lng  = (const float*)d_in[9];
    const float* lnb  = (const float*)d_in[10];
    const float* dist = (const float*)d_in[11];
    const float* dirb = (const float*)d_in[12];

    float* y_out  = (float*)d_out;
    float* aw_out = y_out + (size_t)BATCH * SEQ * DMODEL;

    comb_kernel<<<30, 256>>>(dist, dirb);
    idx_kernel<<<4096, 256>>>();
    conv_kernel<<<(NX + 4 * NW) / 1024, 256>>>(x, wq, wk, wv, wo);
    proj16b_kernel<<<dim3(2, 64, 3), 256>>>(bq, bk, bv);
    qk16_kernel<<<dim3(8, 8, 64), 256>>>();
    softmax_kernel<<<1024, 256>>>(aw_out);
    pv16_kernel<<<dim3(8, 64), 256>>>();
    outproj16_kernel<<<dim3(2, 64), 256>>>();
    ln_kernel<<<8192, 256>>>(x, bo, lng, lnb, y_out);
}

// round 17
// speedup vs baseline: 2.5007x; 1.0409x over previous
#include <cuda_runtime.h>
#include <cuda_fp16.h>
#include <mma.h>

using namespace nvcuda;

#define BATCH  8
#define SEQ    1024
#define DMODEL 256
#define NHD    8
#define DKH    32

// ---------------- scratch (device globals; no allocations) ----------------
__device__ __half g_xh[(size_t)BATCH * SEQ * DMODEL];
__device__ __half g_wqh[DMODEL * DMODEL];
__device__ __half g_wkh[DMODEL * DMODEL];
__device__ __half g_wvh[DMODEL * DMODEL];
__device__ __half g_woh[DMODEL * DMODEL];
__device__ __half g_qh[(size_t)BATCH * SEQ * DMODEL];
__device__ __half g_kh[(size_t)BATCH * SEQ * DMODEL];
__device__ __half g_vh[(size_t)BATCH * SEQ * DMODEL];
__device__ __half g_sh[(size_t)BATCH * NHD * SEQ * SEQ];   // E = exp(s) fp16 (134 MB)
__device__ __half g_ctxh[(size_t)BATCH * SEQ * DMODEL];
__device__ float g_tmp[(size_t)BATCH * SEQ * DMODEL];
__device__ float g_ipw[(size_t)BATCH * NHD * SEQ];         // 0.125 / Zp per (bh,i)
__device__ unsigned short g_idx[SEQ * SEQ];
__device__ float g_cexp[NHD * 960];                        // exp(dist_bias + dir_bias)

// ---------------- fp32 -> fp16 conversion (x, wq, wk, wv, wo) ----------------
#define NX (BATCH * SEQ * DMODEL)
#define NW (DMODEL * DMODEL)
__global__ void conv_kernel(const float* __restrict__ x,
                            const float* __restrict__ wq, const float* __restrict__ wk,
                            const float* __restrict__ wv, const float* __restrict__ wo) {
    int i4 = (blockIdx.x * 256 + threadIdx.x) * 4;
    const float* src; __half* dst; int off;
    if (i4 < NX)               { src = x;  dst = g_xh;  off = i4; }
    else if (i4 < NX + NW)     { src = wq; dst = g_wqh; off = i4 - NX; }
    else if (i4 < NX + 2 * NW) { src = wk; dst = g_wkh; off = i4 - NX - NW; }
    else if (i4 < NX + 3 * NW) { src = wv; dst = g_wvh; off = i4 - NX - 2 * NW; }
    else                       { src = wo; dst = g_woh; off = i4 - NX - 3 * NW; }
    float4 v = *(const float4*)(src + off);
    __half2 h01 = __floats2half2_rn(v.x, v.y);
    __half2 h23 = __floats2half2_rn(v.z, v.w);
    __half2 hv[2] = {h01, h23};
    *(uint2*)(dst + off) = *(uint2*)hv;
}

// ---------------- bias-exp table + spatial index precompute ----------------
__global__ void comb_kernel(const float* __restrict__ dist_bias,
                            const float* __restrict__ dir_bias) {
    int t = blockIdx.x * 256 + threadIdx.x;
    if (t < NHD * 960) {
        int h = t / 960, r = t % 960;
        int di = r >> 4, dr = r & 15;
        g_cexp[t] = __expf(dist_bias[di * NHD + h] + dir_bias[dr * NHD + h]);
    }
}

__global__ void idx_kernel() {
    int e = blockIdx.x * 256 + threadIdx.x;
    int i = e >> 10, j = e & 1023;
    int h1 = i >> 5, w1 = i & 31, h2 = j >> 5, w2 = j & 31;
    int dh = h2 - h1, dw = w2 - w1;
    int n = dh * dh + dw * dw;
    int di = (int)sqrtf((float)n);
    if (di > 59) di = 59;
    int ex = -dw, ey = -dh, dir;
    if (ey == 0)            dir = (ex >= 0) ? 0 : 8;
    else if (ex == 0)       dir = (ey > 0) ? 4 : 12;
    else if (ex == ey)      dir = (ex > 0) ? 2 : 10;
    else if (ex == -ey)     dir = (ex > 0) ? 14 : 6;
    else {
        float a = atan2f((float)ey, (float)ex);
        if (a < 0.0f) a += 6.28318530717958647692f;
        dir = (int)(a * 2.54647908947032537164f);
        if (dir > 15) dir = 15;
    }
    g_idx[e] = (unsigned short)(di * 16 + dir);
}

// ---------------- warp epilogue: f32 accum fragment -> fp16 gmem tile ----------------
template <bool BIAS>
__device__ __forceinline__ void frag_to_half(
    wmma::fragment<wmma::accumulator, 16, 16, 16, float>& acc,
    float (*buf)[20], __half* gp, int ldg, float mult, const float* bias)
{
    wmma::store_matrix_sync(&buf[0][0], acc, 20, wmma::mem_row_major);
    __syncwarp();
    int lane = threadIdx.x & 31;
    int r = lane >> 1, c = (lane & 1) * 8;
    const float* bp = &buf[r][c];
    __half2 hv[4];
#pragma unroll
    for (int j = 0; j < 4; j++) {
        float v0 = bp[2 * j] * mult, v1 = bp[2 * j + 1] * mult;
        if (BIAS) { v0 += bias[c + 2 * j]; v1 += bias[c + 2 * j + 1]; }
        hv[j] = __floats2half2_rn(v0, v1);
    }
    *(uint4*)(gp + (size_t)r * ldg + c) = *(uint4*)hv;
    __syncwarp();
}

// ---------------- QKV projection (fp16 WMMA, fp16 out + bias) ----------------
__global__ __launch_bounds__(256) void proj16b_kernel(
    const float* __restrict__ b0, const float* __restrict__ b1, const float* __restrict__ b2)
{
    __shared__ __align__(32) __half As[128][72];
    __shared__ __align__(32) __half Bs[128][72];
    __shared__ __align__(32) float buf[8][16][20];
    int z = blockIdx.z;
    const __half* A = g_xh;
    const __half* B = (z == 0) ? g_wqh : ((z == 1) ? g_wkh : g_wvh);
    const float* bi = (z == 0) ? b0 : ((z == 1) ? b1 : b2);
    __half* out     = (z == 0) ? g_qh  : ((z == 1) ? g_kh  : g_vh);

    int m0 = blockIdx.y * 128, n0 = blockIdx.x * 128;
    int tid = threadIdx.x;
    const int wid = tid >> 5;
    const int wm = (wid & 3) * 32, wn = (wid >> 2) * 64;

    wmma::fragment<wmma::accumulator, 16, 16, 16, float> acc[2][4];
#pragma unroll
    for (int mi = 0; mi < 2; mi++)
#pragma unroll
        for (int ni = 0; ni < 4; ni++) wmma::fill_fragment(acc[mi][ni], 0.0f);

    for (int kt = 0; kt < DMODEL; kt += 64) {
#pragma unroll
        for (int it = 0; it < 4; it++) {
            int chunk = tid + it * 256;
            int row = chunk >> 3, off = (chunk & 7) * 8;
            *(uint4*)&As[row][off] = *(const uint4*)(A + (size_t)(m0 + row) * DMODEL + kt + off);
            *(uint4*)&Bs[row][off] = *(const uint4*)(B + (size_t)(n0 + row) * DMODEL + kt + off);
        }
        __syncthreads();
#pragma unroll
        for (int ks = 0; ks < 4; ks++) {
            wmma::fragment<wmma::matrix_a, 16, 16, 16, __half, wmma::row_major> af[2];
#pragma unroll
            for (int mi = 0; mi < 2; mi++)
                wmma::load_matrix_sync(af[mi], &As[wm + mi * 16][ks * 16], 72);
            wmma::fragment<wmma::matrix_b, 16, 16, 16, __half, wmma::col_major> bf[4];
#pragma unroll
            for (int ni = 0; ni < 4; ni++)
                wmma::load_matrix_sync(bf[ni], &Bs[wn + ni * 16][ks * 16], 72);
#pragma unroll
            for (int mi = 0; mi < 2; mi++)
#pragma unroll
                for (int ni = 0; ni < 4; ni++)
                    wmma::mma_sync(acc[mi][ni], af[mi], bf[ni], acc[mi][ni]);
        }
        __syncthreads();
    }
#pragma unroll
    for (int mi = 0; mi < 2; mi++)
#pragma unroll
        for (int ni = 0; ni < 4; ni++)
            frag_to_half<true>(acc[mi][ni], buf[wid],
                out + (size_t)(m0 + wm + mi * 16) * DMODEL + n0 + wn + ni * 16,
                DMODEL, 1.0f, bi + n0 + wn + ni * 16);
}

// ---------------- flash: E=exp(QK^T*scale) -> gmem; Zp,Zb; ctx=(E.cexp)@V/Zb ----------------
// dynamic smem layout (bytes):
//   Qs   [128][40]h   @ 0      (10240)
//   Ks   [128][40]h   @ 10240  (10240)
//   Vs   [128][40]h   @ 20480  (10240)
//   Es   [128][136]h  @ 30720  (34816)
//   buf  [8][16][20]f @ 65536  (10240)
//   cexp [960]f       @ 75776  (3840)
//   zps  [128][2]f    @ 79616  (1024)
//   zbs  [128][2]f    @ 80640  (1024)
//   invzb[128]f       @ 81664  (512)
#define FLASH_SMEM 82176

__global__ __launch_bounds__(256) void flash_kernel() {
    extern __shared__ char sm[];
    __half (*Qs)[40]   = (__half (*)[40])(sm);
    __half (*Ks)[40]   = (__half (*)[40])(sm + 10240);
    __half (*Vs)[40]   = (__half (*)[40])(sm + 20480);
    __half (*Es)[136]  = (__half (*)[136])(sm + 30720);
    float (*buf)[16][20] = (float (*)[16][20])(sm + 65536);
    float* cexp_s      = (float*)(sm + 75776);
    float (*zps)[2]    = (float (*)[2])(sm + 79616);
    float (*zbs)[2]    = (float (*)[2])(sm + 80640);
    float* invzb       = (float*)(sm + 81664);

    int bh = blockIdx.y;
    int b = bh >> 3, h = bh & 7;
    int i0 = blockIdx.x * 128;
    int tid = threadIdx.x, lane = tid & 31, wid = tid >> 5;

    const __half* Q = g_qh + (size_t)b * SEQ * DMODEL + h * DKH;
    const __half* K = g_kh + (size_t)b * SEQ * DMODEL + h * DKH;
    const __half* V = g_vh + (size_t)b * SEQ * DMODEL + h * DKH;
    __half* Eg = g_sh + (size_t)bh * SEQ * SEQ;

#pragma unroll
    for (int it = 0; it < 2; it++) {
        int chunk = tid + it * 256;
        int row = chunk >> 2, off = (chunk & 3) * 8;
        *(uint4*)&Qs[row][off] = *(const uint4*)(Q + (size_t)(i0 + row) * DMODEL + off);
    }
    for (int t = tid; t < 960; t += 256) cexp_s[t] = g_cexp[h * 960 + t];

    const int wm = (wid & 3) * 32, wn = (wid >> 2) * 64;
    const int r = lane >> 1, cb = (lane & 1) * 8;
    const float scale = 0.17677669529663688f;

    float zp_r[2] = {0.f, 0.f}, zb_r[2] = {0.f, 0.f};
    wmma::fragment<wmma::accumulator, 16, 16, 16, float> pv[2];
    wmma::fill_fragment(pv[0], 0.0f);
    wmma::fill_fragment(pv[1], 0.0f);

    for (int jt = 0; jt < 8; jt++) {
        int j0 = jt * 128;
        __syncthreads();   // prior PV reads of Ks/Vs/Es done
#pragma unroll
        for (int it = 0; it < 2; it++) {
            int chunk = tid + it * 256;
            int row = chunk >> 2, off = (chunk & 3) * 8;
            *(uint4*)&Ks[row][off] = *(const uint4*)(K + (size_t)(j0 + row) * DMODEL + off);
            *(uint4*)&Vs[row][off] = *(const uint4*)(V + (size_t)(j0 + row) * DMODEL + off);
        }
        __syncthreads();

        // S = Q @ K^T for this 128x128 tile
        wmma::fragment<wmma::accumulator, 16, 16, 16, float> sacc[2][4];
#pragma unroll
        for (int mi = 0; mi < 2; mi++)
#pragma unroll
            for (int ni = 0; ni < 4; ni++) wmma::fill_fragment(sacc[mi][ni], 0.0f);
#pragma unroll
        for (int ks = 0; ks < 2; ks++) {
            wmma::fragment<wmma::matrix_a, 16, 16, 16, __half, wmma::row_major> af[2];
#pragma unroll
            for (int mi = 0; mi < 2; mi++)
                wmma::load_matrix_sync(af[mi], &Qs[wm + mi * 16][ks * 16], 40);
            wmma::fragment<wmma::matrix_b, 16, 16, 16, __half, wmma::col_major> bf[4];
#pragma unroll
            for (int ni = 0; ni < 4; ni++)
                wmma::load_matrix_sync(bf[ni], &Ks[wn + ni * 16][ks * 16], 40);
#pragma unroll
            for (int mi = 0; mi < 2; mi++)
#pragma unroll
                for (int ni = 0; ni < 4; ni++)
                    wmma::mma_sync(sacc[mi][ni], af[mi], bf[ni], sacc[mi][ni]);
        }

        // epilogue: exp, E->gmem, Eb->smem, z partial sums
#pragma unroll
        for (int mi = 0; mi < 2; mi++)
#pragma unroll
            for (int ni = 0; ni < 4; ni++) {
                wmma::store_matrix_sync(&buf[wid][0][0], sacc[mi][ni], 20, wmma::mem_row_major);
                __syncwarp();
                int grow = i0 + wm + mi * 16 + r;
                int gcol = j0 + wn + ni * 16 + cb;
                const float* bp = &buf[wid][r][cb];
                uint4 iv = *(const uint4*)(g_idx + (size_t)grow * SEQ + gcol);
                const unsigned short* id8 = (const unsigned short*)&iv;
                __half2 ev[4], ebv[4];
                float zpl = 0.f, zbl = 0.f;
#pragma unroll
                for (int j = 0; j < 4; j++) {
                    float e0 = __expf(bp[2 * j] * scale);
                    float e1 = __expf(bp[2 * j + 1] * scale);
                    float c0 = cexp_s[id8[2 * j]];
                    float c1 = cexp_s[id8[2 * j + 1]];
                    zpl += e0 + e1;
                    zbl += e0 * c0 + e1 * c1;
                    ev[j]  = __floats2half2_rn(e0, e1);
                    ebv[j] = __floats2half2_rn(e0 * c0, e1 * c1);
                }
                zp_r[mi] += zpl;
                zb_r[mi] += zbl;
                *(uint4*)(Eg + (size_t)grow * SEQ + gcol) = *(uint4*)ev;
                *(uint4*)&Es[wm + mi * 16 + r][wn + ni * 16 + cb] = *(uint4*)ebv;
                __syncwarp();
            }
        __syncthreads();   // Es complete

        // PV accumulate: ctx += Eb @ V
#pragma unroll
        for (int ks = 0; ks < 8; ks++) {
            wmma::fragment<wmma::matrix_a, 16, 16, 16, __half, wmma::row_major> af;
            wmma::load_matrix_sync(af, &Es[wid * 16][ks * 16], 136);
            wmma::fragment<wmma::matrix_b, 16, 16, 16, __half, wmma::row_major> bf[2];
            wmma::load_matrix_sync(bf[0], &Vs[ks * 16][0], 40);
            wmma::load_matrix_sync(bf[1], &Vs[ks * 16][16], 40);
            wmma::mma_sync(pv[0], af, bf[0], pv[0]);
            wmma::mma_sync(pv[1], af, bf[1], pv[1]);
        }
    }

    // combine row sums
#pragma unroll
    for (int mi = 0; mi < 2; mi++) {
        zp_r[mi] += __shfl_xor_sync(0xffffffffu, zp_r[mi], 1);
        zb_r[mi] += __shfl_xor_sync(0xffffffffu, zb_r[mi], 1);
    }
    if ((lane & 1) == 0) {
#pragma unroll
        for (int mi = 0; mi < 2; mi++) {
            zps[wm + mi * 16 + r][wid >> 2] = zp_r[mi];
            zbs[wm + mi * 16 + r][wid >> 2] = zb_r[mi];
        }
    }
    __syncthreads();
    if (tid < 128) {
        float zp = zps[tid][0] + zps[tid][1];
        float zb = zbs[tid][0] + zbs[tid][1];
        g_ipw[(size_t)bh * SEQ + i0 + tid] = 0.125f / zp;
        invzb[tid] = 1.0f / zb;
    }
    __syncthreads();

    // ctx epilogue: scale rows by 1/Zb, store fp16
    __half* outp = g_ctxh + ((size_t)(b * SEQ + i0 + wid * 16)) * DMODEL + h * DKH;
    float rs = invzb[wid * 16 + r];
#pragma unroll
    for (int f = 0; f < 2; f++) {
        wmma::store_matrix_sync(&buf[wid][0][0], pv[f], 20, wmma::mem_row_major);
        __syncwarp();
        const float* bp = &buf[wid][r][cb];
        __half2 hv[4];
#pragma unroll
        for (int j = 0; j < 4; j++)
            hv[j] = __floats2half2_rn(bp[2 * j] * rs, bp[2 * j + 1] * rs);
        *(uint4*)(outp + (size_t)r * DMODEL + f * 16 + cb) = *(uint4*)hv;
        __syncwarp();
    }
}

// ---------------- attn_w = mean_h E / Zp ----------------
__global__ __launch_bounds__(256) void attnw_kernel(float* __restrict__ attn_w) {
    int blk = blockIdx.x;                    // 0..1023
    int b = blk >> 7, i0 = (blk & 127) * 8;
    int tid = threadIdx.x, w = tid >> 5, l = tid & 31;
    int i = i0 + w;
    const int c0 = l * 32;

    float aw[32];
#pragma unroll
    for (int e = 0; e < 32; e++) aw[e] = 0.f;

    for (int h = 0; h < NHD; h++) {
        int bh = b * NHD + h;
        float ipw = g_ipw[(size_t)bh * SEQ + i];
        const __half* erow = g_sh + ((size_t)bh * SEQ + i) * SEQ + c0;
        uint4 raw[4];
#pragma unroll
        for (int t = 0; t < 4; t++) raw[t] = ((const uint4*)erow)[t];
        const __half2* e2 = (const __half2*)raw;
#pragma unroll
        for (int t = 0; t < 16; t++) {
            float2 f = __half22float2(e2[t]);
            aw[2 * t]     += f.x * ipw;
            aw[2 * t + 1] += f.y * ipw;
        }
    }
    float* awp = attn_w + ((size_t)(b * SEQ + i)) * SEQ + c0;
#pragma unroll
    for (int t = 0; t < 8; t++)
        ((float4*)awp)[t] = ((float4*)aw)[t];
}

// ---------------- out-proj: tmp = ctx @ wo^T (f32 out; bias+residual in ln) ----------------
__global__ __launch_bounds__(256) void outproj16_kernel() {
    __shared__ __align__(32) __half As[128][72];
    __shared__ __align__(32) __half Bs[128][72];
    int m0 = blockIdx.y * 128, n0 = blockIdx.x * 128;
    int tid = threadIdx.x;
    const int wid = tid >> 5;
    const int wm = (wid & 3) * 32, wn = (wid >> 2) * 64;

    wmma::fragment<wmma::accumulator, 16, 16, 16, float> acc[2][4];
#pragma unroll
    for (int mi = 0; mi < 2; mi++)
#pragma unroll
        for (int ni = 0; ni < 4; ni++) wmma::fill_fragment(acc[mi][ni], 0.0f);

    for (int kt = 0; kt < DMODEL; kt += 64) {
#pragma unroll
        for (int it = 0; it < 4; it++) {
            int chunk = tid + it * 256;
            int row = chunk >> 3, off = (chunk & 7) * 8;
            *(uint4*)&As[row][off] = *(const uint4*)(g_ctxh + (size_t)(m0 + row) * DMODEL + kt + off);
            *(uint4*)&Bs[row][off] = *(const uint4*)(g_woh  + (size_t)(n0 + row) * DMODEL + kt + off);
        }
        __syncthreads();
#pragma unroll
        for (int ks = 0; ks < 4; ks++) {
            wmma::fragment<wmma::matrix_a, 16, 16, 16, __half, wmma::row_major> af[2];
#pragma unroll
            for (int mi = 0; mi < 2; mi++)
                wmma::load_matrix_sync(af[mi], &As[wm + mi * 16][ks * 16], 72);
            wmma::fragment<wmma::matrix_b, 16, 16, 16, __half, wmma::col_major> bf[4];
#pragma unroll
            for (int ni = 0; ni < 4; ni++)
                wmma::load_matrix_sync(bf[ni], &Bs[wn + ni * 16][ks * 16], 72);
#pragma unroll
            for (int mi = 0; mi < 2; mi++)
#pragma unroll
                for (int ni = 0; ni < 4; ni++)
                    wmma::mma_sync(acc[mi][ni], af[mi], bf[ni], acc[mi][ni]);
        }
        __syncthreads();
    }
#pragma unroll
    for (int mi = 0; mi < 2; mi++)
#pragma unroll
        for (int ni = 0; ni < 4; ni++)
            wmma::store_matrix_sync(
                g_tmp + (size_t)(m0 + wm + mi * 16) * DMODEL + n0 + wn + ni * 16,
                acc[mi][ni], DMODEL, wmma::mem_row_major);
}

// ---------------- LayerNorm (adds out-proj bias + residual) ----------------
__device__ __forceinline__ float warp_red_sum(float v) {
#pragma unroll
    for (int o = 16; o; o >>= 1) v += __shfl_xor_sync(0xffffffffu, v, o);
    return v;
}
__global__ __launch_bounds__(256) void ln_kernel(
    const float* __restrict__ x, const float* __restrict__ bo,
    const float* __restrict__ lng, const float* __restrict__ lnb, float* __restrict__ y)
{
    __shared__ float red[8];
    size_t m = blockIdx.x;
    int tid = threadIdx.x, wd = tid >> 5, l = tid & 31;
    float v = g_tmp[m * DMODEL + tid] + bo[tid] + x[m * DMODEL + tid];
    float s = warp_red_sum(v);
    if (l == 0) red[wd] = s;
    __syncthreads();
    float mu = 0.f;
#pragma unroll
    for (int k = 0; k < 8; k++) mu += red[k];
    mu *= (1.0f / DMODEL);
    __syncthreads();
    float d = v - mu;
    float sq = warp_red_sum(d * d);
    if (l == 0) red[wd] = sq;
    __syncthreads();
    float var = 0.f;
#pragma unroll
    for (int k = 0; k < 8; k++) var += red[k];
    var *= (1.0f / DMODEL);
    y[m * DMODEL + tid] = d * rsqrtf(var + 1e-5f) * lng[tid] + lnb[tid];
}

// ---------------- launch ----------------
extern "C" void kernel_launch(void* const* d_in, const int* in_sizes, int n_in,
                              void* d_out, int out_size) {
    const float* x    = (const float*)d_in[0];
    const float* wq   = (const float*)d_in[1];
    const float* bq   = (const float*)d_in[2];
    const float* wk   = (const float*)d_in[3];
    const float* bk   = (const float*)d_in[4];
    const float* wv   = (const float*)d_in[5];
    const float* bv   = (const float*)d_in[6];
    const float* wo   = (const float*)d_in[7];
    const float* bo   = (const float*)d_in[8];
    const float* lng  = (const float*)d_in[9];
    const float* lnb  = (const float*)d_in[10];
    const float* dist = (const float*)d_in[11];
    const float* dirb = (const float*)d_in[12];

    float* y_out  = (float*)d_out;
    float* aw_out = y_out + (size_t)BATCH * SEQ * DMODEL;

    static bool attr_set = false;
    if (!attr_set) {
        cudaFuncSetAttribute(flash_kernel,
                             cudaFuncAttributeMaxDynamicSharedMemorySize, FLASH_SMEM);
        attr_set = true;
    }

    comb_kernel<<<30, 256>>>(dist, dirb);
    idx_kernel<<<4096, 256>>>();
    conv_kernel<<<(NX + 4 * NW) / 1024, 256>>>(x, wq, wk, wv, wo);
    proj16b_kernel<<<dim3(2, 64, 3), 256>>>(bq, bk, bv);
    flash_kernel<<<dim3(8, 64), 256, FLASH_SMEM>>>();
    attnw_kernel<<<1024, 256>>>(aw_out);
    outproj16_kernel<<<dim3(2, 64), 256>>>();
    ln_kernel<<<8192, 256>>>(x, bo, lng, lnb, y_out);
}